// round 12
// baseline (speedup 1.0000x reference)
#include <cuda_runtime.h>
#include <cuda_bf16.h>
#include <cstring>
#include <math.h>
#include <stdint.h>

#define S_  1024
#define B_  64
#define H_  1024
#define E_  512
#define V_  32000
#define EH_ 1536

typedef unsigned long long ull;

// ---------------- scratch (device globals; no runtime allocation) -------------
__device__ float g_x[B_*H_];
__device__ float g_base[B_*H_];
__device__ float g_scores[B_*S_];
__device__ float g_attn[B_*S_];
__device__ float g_logits[B_*V_];
__device__ float g_xcat[B_*EH_];
__device__ float g_px[12*B_*H_];
__device__ float g_pgi[8*B_*3*H_];
__device__ float g_pgh[8*B_*3*H_];
// 15-bit 2-digit int8 quantized operands for the attention GEMM
__device__ signed char g_qah[S_*B_*H_];   // ss hi digit   (64 MB)
__device__ signed char g_qal[S_*B_*H_];   // ss lo digit   (64 MB)
__device__ signed char g_qwh[H_*H_];      // Was hi digit  (1 MB)
__device__ signed char g_qwl[H_*H_];      // Was lo digit  (1 MB)

// ---------------- output layout ----------------------------------------------
#define OFF_PGEN  0
#define OFF_VOCAB 64
#define OFF_HNEW  (OFF_VOCAB + B_*V_)
#define OFF_CTX   (OFF_HNEW + B_*H_)
#define OFF_ATTN  (OFF_CTX  + B_*H_)
#define OFF_COV   (OFF_ATTN + B_*S_)

// ---------------- generic helpers --------------------------------------------
__device__ __forceinline__ void ffma2(ull& acc, ull a, ull b) {
    asm("fma.rn.f32x2 %0, %1, %2, %0;" : "+l"(acc) : "l"(a), "l"(b));
}
__device__ __forceinline__ ull pk2(float x, float y) {
    float2 f = make_float2(x, y); ull u; memcpy(&u, &f, 8); return u;
}
__device__ __forceinline__ float2 upk2(ull u) {
    float2 f; memcpy(&f, &u, 8); return f;
}
__device__ __forceinline__ float wredsum(float v) {
    #pragma unroll
    for (int o = 16; o; o >>= 1) v += __shfl_down_sync(0xffffffffu, v, o);
    return v;
}
__device__ __forceinline__ float wredmax(float v) {
    #pragma unroll
    for (int o = 16; o; o >>= 1) v = fmaxf(v, __shfl_down_sync(0xffffffffu, v, o));
    return v;
}
__device__ __forceinline__ float blockSum(float v, float* red) {
    int lane = threadIdx.x & 31, wid = threadIdx.x >> 5, nw = blockDim.x >> 5;
    v = wredsum(v);
    __syncthreads();
    if (lane == 0) red[wid] = v;
    __syncthreads();
    if (wid == 0) {
        float r = (lane < nw) ? red[lane] : 0.f;
        r = wredsum(r);
        if (lane == 0) red[0] = r;
    }
    __syncthreads();
    return red[0];
}
__device__ __forceinline__ float blockMax(float v, float* red) {
    int lane = threadIdx.x & 31, wid = threadIdx.x >> 5, nw = blockDim.x >> 5;
    v = wredmax(v);
    __syncthreads();
    if (lane == 0) red[wid] = v;
    __syncthreads();
    if (wid == 0) {
        float r = (lane < nw) ? red[lane] : -1e30f;
        r = wredmax(r);
        if (lane == 0) red[0] = r;
    }
    __syncthreads();
    return red[0];
}
__device__ __forceinline__ uint32_t smem_to_u32(const void* p) {
    uint32_t a;
    asm("{ .reg .u64 t; cvta.to.shared.u64 t, %1; cvt.u32.u64 %0, t; }"
        : "=r"(a) : "l"(p));
    return a;
}

// ---------------- MMA / async-copy helpers ------------------------------------
#define LDSM4(R, addr) \
    asm volatile("ldmatrix.sync.aligned.m8n8.x4.shared.b16 {%0,%1,%2,%3}, [%4];" \
        : "=r"((R)[0]), "=r"((R)[1]), "=r"((R)[2]), "=r"((R)[3]) : "r"(addr))

#define IMMA16832(D, A, Bp) \
    asm volatile("mma.sync.aligned.m16n8k32.row.col.s32.s8.s8.s32 " \
        "{%0,%1,%2,%3}, {%4,%5,%6,%7}, {%8,%9}, {%0,%1,%2,%3};" \
        : "+r"((D)[0]), "+r"((D)[1]), "+r"((D)[2]), "+r"((D)[3]) \
        : "r"((A)[0]), "r"((A)[1]), "r"((A)[2]), "r"((A)[3]), \
          "r"((Bp)[0]), "r"((Bp)[1]))

#define CPA16(dst, src) \
    asm volatile("cp.async.cg.shared.global [%0], [%1], 16;" \
        :: "r"(dst), "l"(src) : "memory")
#define CPA_COMMIT() asm volatile("cp.async.commit_group;" ::: "memory")
#define CPA_WAIT0()  asm volatile("cp.async.wait_group 0;" ::: "memory")

// 15-bit 2-digit quantize: v = round(x*scale) clamped, v = 128*h + l
__device__ __forceinline__ void q15(float x, float scale, signed char& h, signed char& l) {
    int v = __float2int_rn(x * scale);
    v = max(-16256, min(16256, v));
    int hi = (v + 64) >> 7;
    h = (signed char)hi;
    l = (signed char)(v - (hi << 7));
}

// ---------------- quantize pre-passes -----------------------------------------
__global__ void k_q_ss(const float* __restrict__ src) {
    int i = blockIdx.x * blockDim.x + threadIdx.x;   // float4 index
    float4 v = ((const float4*)src)[i];
    char4 h, l;
    q15(v.x, 2048.f, h.x, l.x); q15(v.y, 2048.f, h.y, l.y);
    q15(v.z, 2048.f, h.z, l.z); q15(v.w, 2048.f, h.w, l.w);
    ((char4*)g_qah)[i] = h;
    ((char4*)g_qal)[i] = l;
}
__global__ void k_q_was(const float* __restrict__ src) {
    int i = blockIdx.x * blockDim.x + threadIdx.x;
    float4 v = ((const float4*)src)[i];
    char4 h, l;
    q15(v.x, 32768.f, h.x, l.x); q15(v.y, 32768.f, h.y, l.y);
    q15(v.z, 32768.f, h.z, l.z); q15(v.w, 32768.f, h.w, l.w);
    ((char4*)g_qwh)[i] = h;
    ((char4*)g_qwl)[i] = l;
}

// ---------------- batch-shared small GEMM (K-split partials) ------------------
__global__ __launch_bounds__(256) void k_g64(
    const float* __restrict__ A1, const float* __restrict__ W1, float* __restrict__ O1,
    const float* __restrict__ A2, const float* __restrict__ W2, float* __restrict__ O2,
    int lda, int Nld, int klen) {
    const float* A = blockIdx.z ? A2 : A1;
    const float* W = blockIdx.z ? W2 : W1;
    float*       O = blockIdx.z ? O2 : O1;
    __shared__ float am[64][32];
    __shared__ float wsm[32][132];
    int tid = threadIdx.x;
    int tx = tid & 15, ty = tid >> 4;
    int vc = blockIdx.x * 128;
    int kbeg = blockIdx.y * klen;
    int lr = tid >> 2, lk8 = tid & 3;
    int lc = tid >> 1, lh = tid & 1;
    ull acc[4][4];
    #pragma unroll
    for (int r = 0; r < 4; r++)
        #pragma unroll
        for (int j = 0; j < 4; j++) acc[r][j] = pk2(0.f, 0.f);

    for (int k0 = kbeg; k0 < kbeg + klen; k0 += 32) {
        __syncthreads();
        {
            const float* srcb = A + (long)lr * lda + k0;
            *(float4*)&am[lr][lk8 * 8]     = *(const float4*)(srcb + lk8 * 8);
            *(float4*)&am[lr][lk8 * 8 + 4] = *(const float4*)(srcb + lk8 * 8 + 4);
        }
        {
            const float4* src = (const float4*)(W + (long)(vc + lc) * lda + k0 + lh * 16);
            #pragma unroll
            for (int q = 0; q < 4; q++) {
                float4 v = src[q];
                int kk = lh * 16 + q * 4;
                wsm[kk + 0][lc] = v.x; wsm[kk + 1][lc] = v.y;
                wsm[kk + 2][lc] = v.z; wsm[kk + 3][lc] = v.w;
            }
        }
        __syncthreads();
        #pragma unroll
        for (int k = 0; k < 32; k++) {
            const ull* wp = (const ull*)&wsm[k][tx * 8];
            ull w0 = wp[0], w1 = wp[1], w2 = wp[2], w3 = wp[3];
            #pragma unroll
            for (int r = 0; r < 4; r++) {
                float av = am[ty + r * 16][k];
                ull aa = pk2(av, av);
                ffma2(acc[r][0], aa, w0); ffma2(acc[r][1], aa, w1);
                ffma2(acc[r][2], aa, w2); ffma2(acc[r][3], aa, w3);
            }
        }
    }
    long obase = (long)blockIdx.y * 64 * Nld;
    #pragma unroll
    for (int r = 0; r < 4; r++) {
        int brow = ty + r * 16;
        #pragma unroll
        for (int j = 0; j < 4; j++) {
            float2 f = upk2(acc[r][j]);
            int v = vc + tx * 8 + 2 * j;
            O[obase + (long)brow * Nld + v]     = f.x;
            O[obase + (long)brow * Nld + v + 1] = f.y;
        }
    }
}

// ---------------- small elementwise kernels -----------------------------------
__global__ void k_xcat(const float* __restrict__ etab, const int* __restrict__ ids,
                       const float* __restrict__ ctx) {
    int i = blockIdx.x * 256 + threadIdx.x;
    int r = i / 384, q = i % 384;
    float4 v = (q < 128) ? ((const float4*)(etab + (long)ids[r] * E_))[q]
                         : ((const float4*)(ctx + r * H_))[q - 128];
    ((float4*)g_xcat)[i] = v;
}
__global__ void k_xsum(const float* __restrict__ bic) {
    int i = blockIdx.x * 256 + threadIdx.x;
    float a = bic[i & 1023];
    #pragma unroll
    for (int p = 0; p < 12; p++) a += g_px[(long)p * B_ * H_ + i];
    g_x[i] = a;
}
__global__ void k_gates(const float* __restrict__ hidden, const float* __restrict__ bih,
                        const float* __restrict__ bhh, float* __restrict__ hnew) {
    int idx = blockIdx.x * 256 + threadIdx.x;
    int b = idx >> 10, i = idx & 1023;
    long o = (long)b * 3 * H_ + i;
    const long P = (long)B_ * 3 * H_;
    float ir = bih[i], iz = bih[i + H_], in_ = bih[i + 2*H_];
    float hr = bhh[i], hz = bhh[i + H_], hn  = bhh[i + 2*H_];
    #pragma unroll
    for (int p = 0; p < 8; p++) {
        long q = p * P + o;
        ir  += g_pgi[q];        iz += g_pgi[q + H_];    in_ += g_pgi[q + 2*H_];
        hr  += g_pgh[q];        hz += g_pgh[q + H_];    hn  += g_pgh[q + 2*H_];
    }
    float r = 1.f / (1.f + expf(-(ir + hr)));
    float z = 1.f / (1.f + expf(-(iz + hz)));
    float n = tanhf(in_ + r * hn);
    hnew[idx] = (1.f - z) * n + z * hidden[idx];
}
__global__ void k_basesum(const float* __restrict__ bah, const float* __restrict__ bas,
                          const float* __restrict__ bac) {
    int i = blockIdx.x * 256 + threadIdx.x;
    int h = i & 1023;
    float a = bah[h] + bas[h] + bac[h];
    #pragma unroll
    for (int p = 0; p < 8; p++) a += g_px[(long)p * B_ * H_ + i];
    g_base[i] = a;
}

// ---------------- K4: int8 IMMA attention-score GEMM --------------------------
// D = 2^-12*c1 + 2^-19*c2 + 2^-26*c3 where c1=hh, c2=hl+lh, c3=ll (all exact int)
#define ROWB 48                       // 32 data bytes + 16 pad (conflict-free)
#define OFF_AH 0
#define OFF_AL (128*ROWB)             // 6144
#define OFF_BH (2*128*ROWB)           // 12288
#define OFF_BL (OFF_BH + 32*ROWB)     // 13824
#define STAGE  (OFF_BL + 32*ROWB)     // 15360
#define SMEM_SC (2*STAGE + 1024)

// copy one chunk (np,kc): A 128x32 hi/lo + B 32x32 hi/lo
__device__ __forceinline__ void sc_copy(uint32_t sb, int stage, int b, int s0,
                                        int cc, int tid) {
    int np = cc >> 5, kc = cc & 31;
    int n0 = np * 32, k0 = kc * 32;
    uint32_t dst = sb + stage * STAGE;
    int row = tid >> 1, half = tid & 1;
    long aoffg = ((long)(s0 + row) * B_ + b) * H_ + k0 + half * 16;
    CPA16(dst + OFF_AH + row * ROWB + half * 16, g_qah + aoffg);
    CPA16(dst + OFF_AL + row * ROWB + half * 16, g_qal + aoffg);
    if (tid < 128) {
        int which = tid >> 6;            // 0: Bh, 1: Bl
        int c = tid & 63;
        int brow = c >> 1, bhalf = c & 1;
        long boffg = (long)(n0 + brow) * H_ + k0 + bhalf * 16;
        const signed char* src = which ? g_qwl + boffg : g_qwh + boffg;
        uint32_t d = dst + (which ? OFF_BL : OFF_BH) + brow * ROWB + bhalf * 16;
        CPA16(d, src);
    }
}

__global__ __launch_bounds__(256, 2) void k_scores_mma(
    const float* __restrict__ cov, const float* __restrict__ wac,
    const float* __restrict__ wsq, const float* __restrict__ bsq) {
    extern __shared__ __align__(16) char sm[];
    uint32_t sb = smem_to_u32(sm);
    float* red2 = (float*)(sm + 2 * STAGE);

    int tid = threadIdx.x, L = tid & 31, wid = tid >> 5;
    int wm = wid >> 1, wn = wid & 1;
    int b = blockIdx.y, s0 = blockIdx.x * 128;

    uint32_t aoff = ((L & 7) + ((L >> 3) & 1) * 8) * ROWB + ((L >> 4) & 1) * 16;
    uint32_t boff = ((L & 7) + ((L >> 4) & 1) * 8) * ROWB + ((L >> 3) & 1) * 16;

    float cov4[2][2];
    #pragma unroll
    for (int mt = 0; mt < 2; mt++)
        #pragma unroll
        for (int h = 0; h < 2; h++)
            cov4[mt][h] = cov[b * S_ + s0 + wm*32 + mt*16 + h*8 + (L >> 2)];

    float rs[2][2] = {{0.f, 0.f}, {0.f, 0.f}};
    uint32_t c1[2][2][4], c2[2][2][4], c3[2][2][4];

    const float W1 = 2.44140625e-4f;        // 2^-12
    const float W2 = 1.9073486328125e-6f;   // 2^-19
    const float W3 = 1.490116119384766e-8f; // 2^-26

    sc_copy(sb, 0, b, s0, 0, tid);
    CPA_COMMIT();

    for (int cc = 0; cc < 1024; cc++) {       // 32 np * 32 k-chunks
        int kc = cc & 31, np = cc >> 5;
        if (kc == 0) {
            #pragma unroll
            for (int mt = 0; mt < 2; mt++)
                #pragma unroll
                for (int t = 0; t < 2; t++)
                    #pragma unroll
                    for (int j = 0; j < 4; j++) {
                        c1[mt][t][j] = 0u; c2[mt][t][j] = 0u; c3[mt][t][j] = 0u;
                    }
        }
        CPA_WAIT0();
        __syncthreads();
        if (cc + 1 < 1024) sc_copy(sb, (cc + 1) & 1, b, s0, cc + 1, tid);
        CPA_COMMIT();

        uint32_t st = sb + (cc & 1) * STAGE;
        uint32_t ah[2][4], al[2][4];
        #pragma unroll
        for (int mt = 0; mt < 2; mt++) {
            uint32_t abase = (wm*32 + mt*16) * ROWB + aoff;
            LDSM4(ah[mt], st + OFF_AH + abase);
            LDSM4(al[mt], st + OFF_AL + abase);
        }
        uint32_t bhf[4], blf[4];
        uint32_t bbase = (wn*16) * ROWB + boff;
        LDSM4(bhf, st + OFF_BH + bbase);
        LDSM4(blf, st + OFF_BL + bbase);
        #pragma unroll
        for (int mt = 0; mt < 2; mt++) {
            #pragma unroll
            for (int t = 0; t < 2; t++) {
                IMMA16832(c1[mt][t], ah[mt], bhf + t*2);
                IMMA16832(c2[mt][t], ah[mt], blf + t*2);
                IMMA16832(c2[mt][t], al[mt], bhf + t*2);
                IMMA16832(c3[mt][t], al[mt], blf + t*2);
            }
        }
        if (kc == 31) {
            int n0 = np * 32;
            #pragma unroll
            for (int mt = 0; mt < 2; mt++) {
                #pragma unroll
                for (int t = 0; t < 2; t++) {
                    int g = n0 + wn*16 + t*8 + (L & 3) * 2;
                    float q0 = wsq[g],  q1 = wsq[g + 1];
                    float e0 = g_base[b*H_ + g], e1 = g_base[b*H_ + g + 1];
                    float w0 = wac[g],  w1 = wac[g + 1];
                    float d0 = W1*(float)(int)c1[mt][t][0] + W2*(float)(int)c2[mt][t][0] + W3*(float)(int)c3[mt][t][0];
                    float d1 = W1*(float)(int)c1[mt][t][1] + W2*(float)(int)c2[mt][t][1] + W3*(float)(int)c3[mt][t][1];
                    float d2 = W1*(float)(int)c1[mt][t][2] + W2*(float)(int)c2[mt][t][2] + W3*(float)(int)c3[mt][t][2];
                    float d3 = W1*(float)(int)c1[mt][t][3] + W2*(float)(int)c2[mt][t][3] + W3*(float)(int)c3[mt][t][3];
                    rs[mt][0] += q0 * tanhf(d0 + e0 + cov4[mt][0] * w0)
                               + q1 * tanhf(d1 + e1 + cov4[mt][0] * w1);
                    rs[mt][1] += q0 * tanhf(d2 + e0 + cov4[mt][1] * w0)
                               + q1 * tanhf(d3 + e1 + cov4[mt][1] * w1);
                }
            }
        }
    }
    #pragma unroll
    for (int mt = 0; mt < 2; mt++)
        #pragma unroll
        for (int h = 0; h < 2; h++) {
            float v = rs[mt][h];
            v += __shfl_xor_sync(0xffffffffu, v, 1);
            v += __shfl_xor_sync(0xffffffffu, v, 2);
            rs[mt][h] = v;
        }
    __syncthreads();
    if ((L & 3) == 0) {
        #pragma unroll
        for (int mt = 0; mt < 2; mt++)
            #pragma unroll
            for (int h = 0; h < 2; h++)
                red2[wn*128 + wm*32 + mt*16 + h*8 + (L >> 2)] = rs[mt][h];
    }
    __syncthreads();
    if (tid < 128)
        g_scores[b * S_ + s0 + tid] = red2[tid] + red2[128 + tid] + bsq[0];
}

// ---------------- K5: attention softmax chain + coverage ---------------------
__global__ void k_attnsm(const float* __restrict__ coverage, const int* __restrict__ story,
                         float* __restrict__ out) {
    __shared__ float red[32];
    int b = blockIdx.x, t = threadIdx.x;
    float sc = g_scores[b * S_ + t];
    float m = (story[b * S_ + t] > 0) ? 1.f : 0.f;
    float mx = blockMax(sc, red);
    float e = expf(sc - mx);
    float sum = blockSum(e, red);
    float p = (e / sum) * m;
    float s2 = blockSum(p, red);
    float attn = p / s2;
    g_attn[b * S_ + t] = attn;
    out[OFF_COV + b * S_ + t] = coverage[b * S_ + t] + attn;
    float mx2 = blockMax(attn, red);
    float e2 = expf(attn - mx2);
    float s3 = blockSum(e2, red);
    out[OFF_ATTN + b * S_ + t] = e2 / s3;
}

// ---------------- K6: ctx = attn @ story_states ------------------------------
__global__ void k_ctx(const float* __restrict__ ss, float* __restrict__ out) {
    __shared__ float sa[S_];
    int b = blockIdx.y;
    int h = blockIdx.x * 256 + threadIdx.x;
    for (int i = threadIdx.x; i < S_; i += 256) sa[i] = g_attn[b * S_ + i];
    __syncthreads();
    float acc = 0.f;
    #pragma unroll 8
    for (int s = 0; s < S_; s++) acc += sa[s] * ss[((long)s * B_ + b) * H_ + h];
    out[OFF_CTX + b * H_ + h] = acc;
}

// ---------------- K7: pointer-gen gate ---------------------------------------
__global__ void k_pgen(const float* __restrict__ Wpg, const float* __restrict__ bpg,
                       float* __restrict__ out) {
    __shared__ float red[32];
    int b = blockIdx.x, t = threadIdx.x;
    float acc = 0.f;
    for (int k = t; k < H_; k += 256)
        acc += (g_x[b*H_ + k] + out[OFF_CTX + b*H_ + k] + out[OFF_HNEW + b*H_ + k]) * Wpg[k];
    float s = blockSum(acc, red);
    if (t == 0) out[OFF_PGEN + b] = 1.f / (1.f + expf(-(s + bpg[0])));
}

// ---------------- K8: vocab logits GEMM [64 x 32000, K=2048] -----------------
#define KT 32
#define C4 128
__global__ __launch_bounds__(256) void k_logits(
    const float* __restrict__ hnew, const float* __restrict__ ctx,
    const float* __restrict__ Wout, const float* __restrict__ bout) {
    __shared__ float am[64][KT];
    __shared__ float wsm[KT][C4 + 4];
    int tid = threadIdx.x;
    int tx = tid & 15, ty = tid >> 4;
    int vc = blockIdx.x * C4;
    int lr = tid >> 2, lk8 = tid & 3;
    int lc = tid >> 1, lh = tid & 1;
    ull acc[4][4];
    #pragma unroll
    for (int r = 0; r < 4; r++)
        #pragma unroll
        for (int j = 0; j < 4; j++) acc[r][j] = pk2(0.f, 0.f);

    for (int k0 = 0; k0 < 2 * H_; k0 += KT) {
        __syncthreads();
        {
            const float* srcb = (k0 < H_) ? (hnew + lr * H_ + k0)
                                          : (ctx + lr * H_ + (k0 - H_));
            *(float4*)&am[lr][lk8 * 8]     = *(const float4*)(srcb + lk8 * 8);
            *(float4*)&am[lr][lk8 * 8 + 4] = *(const float4*)(srcb + lk8 * 8 + 4);
        }
        {
            const float4* src = (const float4*)&Wout[(long)(vc + lc) * (2*H_) + k0 + lh * 16];
            #pragma unroll
            for (int q = 0; q < 4; q++) {
                float4 v = src[q];
                int kk = lh * 16 + q * 4;
                wsm[kk + 0][lc] = v.x; wsm[kk + 1][lc] = v.y;
                wsm[kk + 2][lc] = v.z; wsm[kk + 3][lc] = v.w;
            }
        }
        __syncthreads();
        #pragma unroll
        for (int k = 0; k < KT; k++) {
            const ull* wp = (const ull*)&wsm[k][tx * 8];
            ull w0 = wp[0], w1 = wp[1], w2 = wp[2], w3 = wp[3];
            #pragma unroll
            for (int r = 0; r < 4; r++) {
                float av = am[ty + r * 16][k];
                ull aa = pk2(av, av);
                ffma2(acc[r][0], aa, w0); ffma2(acc[r][1], aa, w1);
                ffma2(acc[r][2], aa, w2); ffma2(acc[r][3], aa, w3);
            }
        }
    }
    #pragma unroll
    for (int r = 0; r < 4; r++) {
        int brow = ty + r * 16;
        #pragma unroll
        for (int j = 0; j < 4; j++) {
            float2 f = upk2(acc[r][j]);
            int v = vc + tx * 8 + 2 * j;
            g_logits[(long)brow * V_ + v]     = f.x + bout[v];
            g_logits[(long)brow * V_ + v + 1] = f.y + bout[v + 1];
        }
    }
}

// ---------------- K9: vocab softmax ------------------------------------------
__global__ void k_vocabsm(float* __restrict__ out) {
    __shared__ float red[32];
    int b = blockIdx.x, t = threadIdx.x;
    const float* lg = g_logits + (long)b * V_;
    float* vo = out + OFF_VOCAB + (long)b * V_;
    float mx = -1e30f;
    for (int v = t; v < V_; v += 1024) mx = fmaxf(mx, lg[v]);
    mx = blockMax(mx, red);
    float sum = 0.f;
    for (int v = t; v < V_; v += 1024) { float e = expf(lg[v] - mx); vo[v] = e; sum += e; }
    sum = blockSum(sum, red);
    float inv = 1.f / sum;
    for (int v = t; v < V_; v += 1024) vo[v] *= inv;
}

// ---------------- launch ------------------------------------------------------
extern "C" void kernel_launch(void* const* d_in, const int* in_sizes, int n_in,
                              void* d_out, int out_size) {
    (void)in_sizes; (void)n_in; (void)out_size;
    const float* ss       = (const float*)d_in[0];
    const int*   story    = (const int*)  d_in[1];
    const int*   ids      = (const int*)  d_in[2];
    const float* hidden   = (const float*)d_in[3];
    const float* context  = (const float*)d_in[4];
    const float* coverage = (const float*)d_in[5];
    const float* etab     = (const float*)d_in[6];
    const float* Wic = (const float*)d_in[7];   const float* bic = (const float*)d_in[8];
    const float* Wah = (const float*)d_in[9];   const float* bah = (const float*)d_in[10];
    const float* Was = (const float*)d_in[11];  const float* bas = (const float*)d_in[12];
    const float* Wac = (const float*)d_in[13];  const float* bac = (const float*)d_in[14];
    const float* Wsq = (const float*)d_in[15];  const float* bsq = (const float*)d_in[16];
    const float* Wpg = (const float*)d_in[17];  const float* bpg = (const float*)d_in[18];
    const float* Wih = (const float*)d_in[19];  const float* Whh = (const float*)d_in[20];
    const float* bih = (const float*)d_in[21];  const float* bhh = (const float*)d_in[22];
    const float* Wout = (const float*)d_in[23]; const float* bout = (const float*)d_in[24];
    float* out = (float*)d_out;
    float* hnew = out + OFF_HNEW;

    static int smem_set = 0;
    if (!smem_set) {
        cudaFuncSetAttribute(k_scores_mma, cudaFuncAttributeMaxDynamicSharedMemorySize, SMEM_SC);
        smem_set = 1;
    }

    float *p_xcat, *p_x, *p_px, *p_pgi, *p_pgh;
    cudaGetSymbolAddress((void**)&p_xcat, g_xcat);
    cudaGetSymbolAddress((void**)&p_x,    g_x);
    cudaGetSymbolAddress((void**)&p_px,   g_px);
    cudaGetSymbolAddress((void**)&p_pgi,  g_pgi);
    cudaGetSymbolAddress((void**)&p_pgh,  g_pgh);

    k_q_ss <<<(S_*B_*H_/4)/256, 256>>>(ss);
    k_q_was<<<(H_*H_/4)/256, 256>>>(Was);

    k_xcat<<<(B_*EH_/4)/256, 256>>>(etab, ids, context);
    k_g64<<<dim3(H_/128, 12, 1), 256>>>(p_xcat, Wic, p_px, p_xcat, Wic, p_px,
                                        EH_, H_, 128);
    k_xsum<<<B_*H_/256, 256>>>(bic);
    k_g64<<<dim3(3*H_/128, 8, 2), 256>>>(p_x, Wih, p_pgi, hidden, Whh, p_pgh,
                                         H_, 3*H_, 128);
    k_gates<<<B_*H_/256, 256>>>(hidden, bih, bhh, hnew);
    k_g64<<<dim3(H_/128, 8, 1), 256>>>(hnew, Wah, p_px, hnew, Wah, p_px,
                                       H_, H_, 128);
    k_basesum<<<B_*H_/256, 256>>>(bah, bas, bac);

    k_scores_mma<<<dim3(S_/128, B_), 256, SMEM_SC>>>(coverage, Wac, Wsq, bsq);
    k_attnsm<<<B_, S_>>>(coverage, story, out);
    k_ctx<<<dim3(H_/256, B_), 256>>>(ss, out);
    k_pgen<<<B_, 256>>>(Wpg, bpg, out);
    k_logits<<<V_/C4, 256>>>(hnew, out + OFF_CTX, Wout, bout);
    k_vocabsm<<<B_, 1024>>>(out);
}

// round 13
// speedup vs baseline: 2.6061x; 2.6061x over previous
#include <cuda_runtime.h>
#include <cuda_bf16.h>
#include <cstring>
#include <math.h>
#include <stdint.h>

#define S_  1024
#define B_  64
#define H_  1024
#define E_  512
#define V_  32000
#define EH_ 1536

typedef unsigned long long ull;

// ---------------- scratch (device globals; no runtime allocation) -------------
__device__ float g_x[B_*H_];
__device__ float g_base[B_*H_];
__device__ float g_scores[B_*S_];
__device__ float g_attn[B_*S_];
__device__ float g_logits[B_*V_];
__device__ float g_xcat[B_*EH_];
__device__ float g_px[12*B_*H_];
__device__ float g_pgi[8*B_*3*H_];
__device__ float g_pgh[8*B_*3*H_];
// pre-converted split-bf16 operands for the attention GEMM
__device__ __nv_bfloat16 g_ah[S_*B_*H_];
__device__ __nv_bfloat16 g_al[S_*B_*H_];
__device__ __nv_bfloat16 g_wh[H_*H_];
__device__ __nv_bfloat16 g_wl[H_*H_];

// ---------------- output layout ----------------------------------------------
#define OFF_PGEN  0
#define OFF_VOCAB 64
#define OFF_HNEW  (OFF_VOCAB + B_*V_)
#define OFF_CTX   (OFF_HNEW + B_*H_)
#define OFF_ATTN  (OFF_CTX  + B_*H_)
#define OFF_COV   (OFF_ATTN + B_*S_)

// ---------------- generic helpers --------------------------------------------
__device__ __forceinline__ void ffma2(ull& acc, ull a, ull b) {
    asm("fma.rn.f32x2 %0, %1, %2, %0;" : "+l"(acc) : "l"(a), "l"(b));
}
__device__ __forceinline__ ull pk2(float x, float y) {
    float2 f = make_float2(x, y); ull u; memcpy(&u, &f, 8); return u;
}
__device__ __forceinline__ float2 upk2(ull u) {
    float2 f; memcpy(&f, &u, 8); return f;
}
__device__ __forceinline__ float wredsum(float v) {
    #pragma unroll
    for (int o = 16; o; o >>= 1) v += __shfl_down_sync(0xffffffffu, v, o);
    return v;
}
__device__ __forceinline__ float wredmax(float v) {
    #pragma unroll
    for (int o = 16; o; o >>= 1) v = fmaxf(v, __shfl_down_sync(0xffffffffu, v, o));
    return v;
}
__device__ __forceinline__ float blockSum(float v, float* red) {
    int lane = threadIdx.x & 31, wid = threadIdx.x >> 5, nw = blockDim.x >> 5;
    v = wredsum(v);
    __syncthreads();
    if (lane == 0) red[wid] = v;
    __syncthreads();
    if (wid == 0) {
        float r = (lane < nw) ? red[lane] : 0.f;
        r = wredsum(r);
        if (lane == 0) red[0] = r;
    }
    __syncthreads();
    return red[0];
}
__device__ __forceinline__ float blockMax(float v, float* red) {
    int lane = threadIdx.x & 31, wid = threadIdx.x >> 5, nw = blockDim.x >> 5;
    v = wredmax(v);
    __syncthreads();
    if (lane == 0) red[wid] = v;
    __syncthreads();
    if (wid == 0) {
        float r = (lane < nw) ? red[lane] : -1e30f;
        r = wredmax(r);
        if (lane == 0) red[0] = r;
    }
    __syncthreads();
    return red[0];
}
__device__ __forceinline__ uint32_t smem_to_u32(const void* p) {
    uint32_t a;
    asm("{ .reg .u64 t; cvta.to.shared.u64 t, %1; cvt.u32.u64 %0, t; }"
        : "=r"(a) : "l"(p));
    return a;
}

// ---------------- HMMA / async-copy helpers -----------------------------------
#define LDSM4(R, addr) \
    asm volatile("ldmatrix.sync.aligned.m8n8.x4.shared.b16 {%0,%1,%2,%3}, [%4];" \
        : "=r"((R)[0]), "=r"((R)[1]), "=r"((R)[2]), "=r"((R)[3]) : "r"(addr))

#define MMA16816(D, A, Bp) \
    asm volatile("mma.sync.aligned.m16n8k16.row.col.f32.bf16.bf16.f32 " \
        "{%0,%1,%2,%3}, {%4,%5,%6,%7}, {%8,%9}, {%0,%1,%2,%3};" \
        : "+f"((D)[0]), "+f"((D)[1]), "+f"((D)[2]), "+f"((D)[3]) \
        : "r"((A)[0]), "r"((A)[1]), "r"((A)[2]), "r"((A)[3]), \
          "r"((Bp)[0]), "r"((Bp)[1]))

#define CPA16(dst, src) \
    asm volatile("cp.async.cg.shared.global [%0], [%1], 16;" \
        :: "r"(dst), "l"(src) : "memory")
#define CPA_COMMIT() asm volatile("cp.async.commit_group;" ::: "memory")
#define CPA_WAIT0()  asm volatile("cp.async.wait_group 0;" ::: "memory")

__device__ __forceinline__ void bfsplit(float v, unsigned short& h, unsigned short& l) {
    __nv_bfloat16 hh = __float2bfloat16_rn(v);
    float r = v - __bfloat162float(hh);
    __nv_bfloat16 ll = __float2bfloat16_rn(r);
    h = *reinterpret_cast<unsigned short*>(&hh);
    l = *reinterpret_cast<unsigned short*>(&ll);
}

// ---------------- split-convert pre-passes ------------------------------------
__global__ void k_cvt_ss(const float* __restrict__ src) {
    int i = blockIdx.x * blockDim.x + threadIdx.x;
    float4 v = ((const float4*)src)[i];
    ushort4 h, l;
    bfsplit(v.x, h.x, l.x); bfsplit(v.y, h.y, l.y);
    bfsplit(v.z, h.z, l.z); bfsplit(v.w, h.w, l.w);
    ((ushort4*)g_ah)[i] = h;
    ((ushort4*)g_al)[i] = l;
}
__global__ void k_cvt_was(const float* __restrict__ src) {
    int i = blockIdx.x * blockDim.x + threadIdx.x;
    float4 v = ((const float4*)src)[i];
    ushort4 h, l;
    bfsplit(v.x, h.x, l.x); bfsplit(v.y, h.y, l.y);
    bfsplit(v.z, h.z, l.z); bfsplit(v.w, h.w, l.w);
    ((ushort4*)g_wh)[i] = h;
    ((ushort4*)g_wl)[i] = l;
}

// ---------------- batch-shared small GEMM (K-split partials) ------------------
__global__ __launch_bounds__(256) void k_g64(
    const float* __restrict__ A1, const float* __restrict__ W1, float* __restrict__ O1,
    const float* __restrict__ A2, const float* __restrict__ W2, float* __restrict__ O2,
    int lda, int Nld, int klen) {
    const float* A = blockIdx.z ? A2 : A1;
    const float* W = blockIdx.z ? W2 : W1;
    float*       O = blockIdx.z ? O2 : O1;
    __shared__ float am[64][32];
    __shared__ float wsm[32][132];
    int tid = threadIdx.x;
    int tx = tid & 15, ty = tid >> 4;
    int vc = blockIdx.x * 128;
    int kbeg = blockIdx.y * klen;
    int lr = tid >> 2, lk8 = tid & 3;
    int lc = tid >> 1, lh = tid & 1;
    ull acc[4][4];
    #pragma unroll
    for (int r = 0; r < 4; r++)
        #pragma unroll
        for (int j = 0; j < 4; j++) acc[r][j] = pk2(0.f, 0.f);

    for (int k0 = kbeg; k0 < kbeg + klen; k0 += 32) {
        __syncthreads();
        {
            const float* srcb = A + (long)lr * lda + k0;
            *(float4*)&am[lr][lk8 * 8]     = *(const float4*)(srcb + lk8 * 8);
            *(float4*)&am[lr][lk8 * 8 + 4] = *(const float4*)(srcb + lk8 * 8 + 4);
        }
        {
            const float4* src = (const float4*)(W + (long)(vc + lc) * lda + k0 + lh * 16);
            #pragma unroll
            for (int q = 0; q < 4; q++) {
                float4 v = src[q];
                int kk = lh * 16 + q * 4;
                wsm[kk + 0][lc] = v.x; wsm[kk + 1][lc] = v.y;
                wsm[kk + 2][lc] = v.z; wsm[kk + 3][lc] = v.w;
            }
        }
        __syncthreads();
        #pragma unroll
        for (int k = 0; k < 32; k++) {
            const ull* wp = (const ull*)&wsm[k][tx * 8];
            ull w0 = wp[0], w1 = wp[1], w2 = wp[2], w3 = wp[3];
            #pragma unroll
            for (int r = 0; r < 4; r++) {
                float av = am[ty + r * 16][k];
                ull aa = pk2(av, av);
                ffma2(acc[r][0], aa, w0); ffma2(acc[r][1], aa, w1);
                ffma2(acc[r][2], aa, w2); ffma2(acc[r][3], aa, w3);
            }
        }
    }
    long obase = (long)blockIdx.y * 64 * Nld;
    #pragma unroll
    for (int r = 0; r < 4; r++) {
        int brow = ty + r * 16;
        #pragma unroll
        for (int j = 0; j < 4; j++) {
            float2 f = upk2(acc[r][j]);
            int v = vc + tx * 8 + 2 * j;
            O[obase + (long)brow * Nld + v]     = f.x;
            O[obase + (long)brow * Nld + v + 1] = f.y;
        }
    }
}

// ---------------- small elementwise kernels -----------------------------------
__global__ void k_xcat(const float* __restrict__ etab, const int* __restrict__ ids,
                       const float* __restrict__ ctx) {
    int i = blockIdx.x * 256 + threadIdx.x;
    int r = i / 384, q = i % 384;
    float4 v = (q < 128) ? ((const float4*)(etab + (long)ids[r] * E_))[q]
                         : ((const float4*)(ctx + r * H_))[q - 128];
    ((float4*)g_xcat)[i] = v;
}
__global__ void k_xsum(const float* __restrict__ bic) {
    int i = blockIdx.x * 256 + threadIdx.x;
    float a = bic[i & 1023];
    #pragma unroll
    for (int p = 0; p < 12; p++) a += g_px[(long)p * B_ * H_ + i];
    g_x[i] = a;
}
__global__ void k_gates(const float* __restrict__ hidden, const float* __restrict__ bih,
                        const float* __restrict__ bhh, float* __restrict__ hnew) {
    int idx = blockIdx.x * 256 + threadIdx.x;
    int b = idx >> 10, i = idx & 1023;
    long o = (long)b * 3 * H_ + i;
    const long P = (long)B_ * 3 * H_;
    float ir = bih[i], iz = bih[i + H_], in_ = bih[i + 2*H_];
    float hr = bhh[i], hz = bhh[i + H_], hn  = bhh[i + 2*H_];
    #pragma unroll
    for (int p = 0; p < 8; p++) {
        long q = p * P + o;
        ir  += g_pgi[q];        iz += g_pgi[q + H_];    in_ += g_pgi[q + 2*H_];
        hr  += g_pgh[q];        hz += g_pgh[q + H_];    hn  += g_pgh[q + 2*H_];
    }
    float r = 1.f / (1.f + expf(-(ir + hr)));
    float z = 1.f / (1.f + expf(-(iz + hz)));
    float n = tanhf(in_ + r * hn);
    hnew[idx] = (1.f - z) * n + z * hidden[idx];
}
__global__ void k_basesum(const float* __restrict__ bah, const float* __restrict__ bas,
                          const float* __restrict__ bac) {
    int i = blockIdx.x * 256 + threadIdx.x;
    int h = i & 1023;
    float a = bah[h] + bas[h] + bac[h];
    #pragma unroll
    for (int p = 0; p < 8; p++) a += g_px[(long)p * B_ * H_ + i];
    g_base[i] = a;
}

// ---------------- K4: HMMA attention-score GEMM (digit-pass ordering) ---------
#define ROWE 40
#define ROWB (ROWE*2)
#define ARRB (128*ROWB)        // 10240 B per operand tile
#define STAGE (4*ARRB)         // 40960 B per stage
#define SMEM_SC (2*STAGE + 1024)

__device__ __forceinline__ void sc_copy(uint32_t sb, int stage, int b, int s0,
                                        int cc, int tid) {
    int np = cc >> 5, kc = cc & 31;
    int n0 = np * 128, k0 = kc * 32;
    int t64 = tid & 63, arr = tid >> 6;
    uint32_t dbase = sb + stage * STAGE + arr * ARRB;
    const __nv_bfloat16* gsrc;
    long rstride;
    if (arr == 0)      { gsrc = g_ah + ((long)s0 * B_ + b) * H_ + k0; rstride = (long)B_ * H_; }
    else if (arr == 1) { gsrc = g_al + ((long)s0 * B_ + b) * H_ + k0; rstride = (long)B_ * H_; }
    else if (arr == 2) { gsrc = g_wh + (long)n0 * H_ + k0;            rstride = H_; }
    else               { gsrc = g_wl + (long)n0 * H_ + k0;            rstride = H_; }
    #pragma unroll
    for (int j = 0; j < 8; j++) {
        int c = j * 64 + t64;
        int row = c >> 2, q = c & 3;
        CPA16(dbase + row * ROWB + q * 16, (const char*)(gsrc + row * rstride) + q * 16);
    }
}

__global__ __launch_bounds__(256, 2) void k_scores_mma(
    const float* __restrict__ cov, const float* __restrict__ wac,
    const float* __restrict__ wsq, const float* __restrict__ bsq) {
    extern __shared__ __align__(16) char sm[];
    uint32_t sb = smem_to_u32(sm);
    float* red2 = (float*)(sm + 2 * STAGE);

    int tid = threadIdx.x, L = tid & 31, wid = tid >> 5;
    int wm = wid >> 1, wn = wid & 1;
    int b = blockIdx.y, s0 = blockIdx.x * 128;

    uint32_t aoff = ((L & 7) + ((L >> 3) & 1) * 8) * ROWB + ((L >> 4) & 1) * 16;
    uint32_t boff = ((L & 7) + ((L >> 4) & 1) * 8) * ROWB + ((L >> 3) & 1) * 16;

    float cov4[2][2];
    #pragma unroll
    for (int mt = 0; mt < 2; mt++)
        #pragma unroll
        for (int h = 0; h < 2; h++)
            cov4[mt][h] = cov[b * S_ + s0 + wm*32 + mt*16 + h*8 + (L >> 2)];

    float rs[2][2] = {{0.f, 0.f}, {0.f, 0.f}};
    float c[2][8][4];

    // prologue: chunk 0 -> buf 0
    sc_copy(sb, 0, b, s0, 0, tid);
    CPA_COMMIT();

    for (int cc = 0; cc < 256; cc++) {
        int kc = cc & 31, np = cc >> 5;
        if (kc == 0) {
            #pragma unroll
            for (int mt = 0; mt < 2; mt++)
                #pragma unroll
                for (int nt = 0; nt < 8; nt++)
                    #pragma unroll
                    for (int j = 0; j < 4; j++) c[mt][nt][j] = 0.f;
        }
        CPA_WAIT0();
        __syncthreads();
        if (cc + 1 < 256) sc_copy(sb, (cc + 1) & 1, b, s0, cc + 1, tid);
        CPA_COMMIT();

        uint32_t st = sb + (cc & 1) * STAGE;
        uint32_t uAh = st, uAl = st + ARRB, uBh = st + 2*ARRB, uBl = st + 3*ARRB;
        #pragma unroll
        for (int ks = 0; ks < 2; ks++) {
            uint32_t kb = ks * 32;
            uint32_t ah[2][4], al[2][4];
            #pragma unroll
            for (int mt = 0; mt < 2; mt++) {
                uint32_t base = (wm*32 + mt*16) * ROWB + kb;
                LDSM4(ah[mt], uAh + base + aoff);
                LDSM4(al[mt], uAl + base + aoff);
            }
            #pragma unroll
            for (int ph = 0; ph < 2; ph++) {
                uint32_t bh[2][4], bl[2][4];
                #pragma unroll
                for (int q = 0; q < 2; q++) {
                    uint32_t bb = (wn*64 + (ph*2 + q)*16) * ROWB + kb + boff;
                    LDSM4(bh[q], uBh + bb);
                    LDSM4(bl[q], uBl + bb);
                }
                // digit-product passes: 8 distinct accumulators per pass,
                // same-acc reuse distance = 8 MMAs -> latency hidden at rt
                #pragma unroll
                for (int q = 0; q < 2; q++)
                    #pragma unroll
                    for (int mt = 0; mt < 2; mt++)
                        #pragma unroll
                        for (int t = 0; t < 2; t++)
                            MMA16816(c[mt][(ph*2+q)*2 + t], ah[mt], bh[q] + t*2);
                #pragma unroll
                for (int q = 0; q < 2; q++)
                    #pragma unroll
                    for (int mt = 0; mt < 2; mt++)
                        #pragma unroll
                        for (int t = 0; t < 2; t++)
                            MMA16816(c[mt][(ph*2+q)*2 + t], ah[mt], bl[q] + t*2);
                #pragma unroll
                for (int q = 0; q < 2; q++)
                    #pragma unroll
                    for (int mt = 0; mt < 2; mt++)
                        #pragma unroll
                        for (int t = 0; t < 2; t++)
                            MMA16816(c[mt][(ph*2+q)*2 + t], al[mt], bh[q] + t*2);
            }
        }
        if (kc == 31) {
            int n0 = np * 128;
            #pragma unroll
            for (int mt = 0; mt < 2; mt++) {
                #pragma unroll
                for (int nt = 0; nt < 8; nt++) {
                    int g = n0 + wn*64 + nt*8 + (L & 3) * 2;
                    float q0 = wsq[g],  q1 = wsq[g + 1];
                    float e0 = g_base[b*H_ + g], e1 = g_base[b*H_ + g + 1];
                    float w0 = wac[g],  w1 = wac[g + 1];
                    rs[mt][0] += q0 * tanhf(c[mt][nt][0] + e0 + cov4[mt][0] * w0)
                               + q1 * tanhf(c[mt][nt][1] + e1 + cov4[mt][0] * w1);
                    rs[mt][1] += q0 * tanhf(c[mt][nt][2] + e0 + cov4[mt][1] * w0)
                               + q1 * tanhf(c[mt][nt][3] + e1 + cov4[mt][1] * w1);
                }
            }
        }
    }
    #pragma unroll
    for (int mt = 0; mt < 2; mt++)
        #pragma unroll
        for (int h = 0; h < 2; h++) {
            float v = rs[mt][h];
            v += __shfl_xor_sync(0xffffffffu, v, 1);
            v += __shfl_xor_sync(0xffffffffu, v, 2);
            rs[mt][h] = v;
        }
    __syncthreads();
    if ((L & 3) == 0) {
        #pragma unroll
        for (int mt = 0; mt < 2; mt++)
            #pragma unroll
            for (int h = 0; h < 2; h++)
                red2[wn*128 + wm*32 + mt*16 + h*8 + (L >> 2)] = rs[mt][h];
    }
    __syncthreads();
    if (tid < 128)
        g_scores[b * S_ + s0 + tid] = red2[tid] + red2[128 + tid] + bsq[0];
}

// ---------------- K5: attention softmax chain + coverage ---------------------
__global__ void k_attnsm(const float* __restrict__ coverage, const int* __restrict__ story,
                         float* __restrict__ out) {
    __shared__ float red[32];
    int b = blockIdx.x, t = threadIdx.x;
    float sc = g_scores[b * S_ + t];
    float m = (story[b * S_ + t] > 0) ? 1.f : 0.f;
    float mx = blockMax(sc, red);
    float e = expf(sc - mx);
    float sum = blockSum(e, red);
    float p = (e / sum) * m;
    float s2 = blockSum(p, red);
    float attn = p / s2;
    g_attn[b * S_ + t] = attn;
    out[OFF_COV + b * S_ + t] = coverage[b * S_ + t] + attn;
    float mx2 = blockMax(attn, red);
    float e2 = expf(attn - mx2);
    float s3 = blockSum(e2, red);
    out[OFF_ATTN + b * S_ + t] = e2 / s3;
}

// ---------------- K6: ctx = attn @ story_states ------------------------------
__global__ void k_ctx(const float* __restrict__ ss, float* __restrict__ out) {
    __shared__ float sa[S_];
    int b = blockIdx.y;
    int h = blockIdx.x * 256 + threadIdx.x;
    for (int i = threadIdx.x; i < S_; i += 256) sa[i] = g_attn[b * S_ + i];
    __syncthreads();
    float acc = 0.f;
    #pragma unroll 8
    for (int s = 0; s < S_; s++) acc += sa[s] * ss[((long)s * B_ + b) * H_ + h];
    out[OFF_CTX + b * H_ + h] = acc;
}

// ---------------- K7: pointer-gen gate ---------------------------------------
__global__ void k_pgen(const float* __restrict__ Wpg, const float* __restrict__ bpg,
                       float* __restrict__ out) {
    __shared__ float red[32];
    int b = blockIdx.x, t = threadIdx.x;
    float acc = 0.f;
    for (int k = t; k < H_; k += 256)
        acc += (g_x[b*H_ + k] + out[OFF_CTX + b*H_ + k] + out[OFF_HNEW + b*H_ + k]) * Wpg[k];
    float s = blockSum(acc, red);
    if (t == 0) out[OFF_PGEN + b] = 1.f / (1.f + expf(-(s + bpg[0])));
}

// ---------------- K8: vocab logits GEMM [64 x 32000, K=2048] -----------------
#define KT 32
#define C4 128
__global__ __launch_bounds__(256) void k_logits(
    const float* __restrict__ hnew, const float* __restrict__ ctx,
    const float* __restrict__ Wout, const float* __restrict__ bout) {
    __shared__ float am[64][KT];
    __shared__ float wsm[KT][C4 + 4];
    int tid = threadIdx.x;
    int tx = tid & 15, ty = tid >> 4;
    int vc = blockIdx.x * C4;
    int lr = tid >> 2, lk8 = tid & 3;
    int lc = tid >> 1, lh = tid & 1;
    ull acc[4][4];
    #pragma unroll
    for (int r = 0; r < 4; r++)
        #pragma unroll
        for (int j = 0; j < 4; j++) acc[r][j] = pk2(0.f, 0.f);

    for (int k0 = 0; k0 < 2 * H_; k0 += KT) {
        __syncthreads();
        {
            const float* srcb = (k0 < H_) ? (hnew + lr * H_ + k0)
                                          : (ctx + lr * H_ + (k0 - H_));
            *(float4*)&am[lr][lk8 * 8]     = *(const float4*)(srcb + lk8 * 8);
            *(float4*)&am[lr][lk8 * 8 + 4] = *(const float4*)(srcb + lk8 * 8 + 4);
        }
        {
            const float4* src = (const float4*)&Wout[(long)(vc + lc) * (2*H_) + k0 + lh * 16];
            #pragma unroll
            for (int q = 0; q < 4; q++) {
                float4 v = src[q];
                int kk = lh * 16 + q * 4;
                wsm[kk + 0][lc] = v.x; wsm[kk + 1][lc] = v.y;
                wsm[kk + 2][lc] = v.z; wsm[kk + 3][lc] = v.w;
            }
        }
        __syncthreads();
        #pragma unroll
        for (int k = 0; k < KT; k++) {
            const ull* wp = (const ull*)&wsm[k][tx * 8];
            ull w0 = wp[0], w1 = wp[1], w2 = wp[2], w3 = wp[3];
            #pragma unroll
            for (int r = 0; r < 4; r++) {
                float av = am[ty + r * 16][k];
                ull aa = pk2(av, av);
                ffma2(acc[r][0], aa, w0); ffma2(acc[r][1], aa, w1);
                ffma2(acc[r][2], aa, w2); ffma2(acc[r][3], aa, w3);
            }
        }
    }
    #pragma unroll
    for (int r = 0; r < 4; r++) {
        int brow = ty + r * 16;
        #pragma unroll
        for (int j = 0; j < 4; j++) {
            float2 f = upk2(acc[r][j]);
            int v = vc + tx * 8 + 2 * j;
            g_logits[(long)brow * V_ + v]     = f.x + bout[v];
            g_logits[(long)brow * V_ + v + 1] = f.y + bout[v + 1];
        }
    }
}

// ---------------- K9: vocab softmax ------------------------------------------
__global__ void k_vocabsm(float* __restrict__ out) {
    __shared__ float red[32];
    int b = blockIdx.x, t = threadIdx.x;
    const float* lg = g_logits + (long)b * V_;
    float* vo = out + OFF_VOCAB + (long)b * V_;
    float mx = -1e30f;
    for (int v = t; v < V_; v += 1024) mx = fmaxf(mx, lg[v]);
    mx = blockMax(mx, red);
    float sum = 0.f;
    for (int v = t; v < V_; v += 1024) { float e = expf(lg[v] - mx); vo[v] = e; sum += e; }
    sum = blockSum(sum, red);
    float inv = 1.f / sum;
    for (int v = t; v < V_; v += 1024) vo[v] *= inv;
}

// ---------------- launch ------------------------------------------------------
extern "C" void kernel_launch(void* const* d_in, const int* in_sizes, int n_in,
                              void* d_out, int out_size) {
    (void)in_sizes; (void)n_in; (void)out_size;
    const float* ss       = (const float*)d_in[0];
    const int*   story    = (const int*)  d_in[1];
    const int*   ids      = (const int*)  d_in[2];
    const float* hidden   = (const float*)d_in[3];
    const float* context  = (const float*)d_in[4];
    const float* coverage = (const float*)d_in[5];
    const float* etab     = (const float*)d_in[6];
    const float* Wic = (const float*)d_in[7];   const float* bic = (const float*)d_in[8];
    const float* Wah = (const float*)d_in[9];   const float* bah = (const float*)d_in[10];
    const float* Was = (const float*)d_in[11];  const float* bas = (const float*)d_in[12];
    const float* Wac = (const float*)d_in[13];  const float* bac = (const float*)d_in[14];
    const float* Wsq = (const float*)d_in[15];  const float* bsq = (const float*)d_in[16];
    const float* Wpg = (const float*)d_in[17];  const float* bpg = (const float*)d_in[18];
    const float* Wih = (const float*)d_in[19];  const float* Whh = (const float*)d_in[20];
    const float* bih = (const float*)d_in[21];  const float* bhh = (const float*)d_in[22];
    const float* Wout = (const float*)d_in[23]; const float* bout = (const float*)d_in[24];
    float* out = (float*)d_out;
    float* hnew = out + OFF_HNEW;

    static int smem_set = 0;
    if (!smem_set) {
        cudaFuncSetAttribute(k_scores_mma, cudaFuncAttributeMaxDynamicSharedMemorySize, SMEM_SC);
        smem_set = 1;
    }

    float *p_xcat, *p_x, *p_px, *p_pgi, *p_pgh;
    cudaGetSymbolAddress((void**)&p_xcat, g_xcat);
    cudaGetSymbolAddress((void**)&p_x,    g_x);
    cudaGetSymbolAddress((void**)&p_px,   g_px);
    cudaGetSymbolAddress((void**)&p_pgi,  g_pgi);
    cudaGetSymbolAddress((void**)&p_pgh,  g_pgh);

    k_cvt_ss <<<(S_*B_*H_/4)/256, 256>>>(ss);
    k_cvt_was<<<(H_*H_/4)/256, 256>>>(Was);

    k_xcat<<<(B_*EH_/4)/256, 256>>>(etab, ids, context);
    k_g64<<<dim3(H_/128, 12, 1), 256>>>(p_xcat, Wic, p_px, p_xcat, Wic, p_px,
                                        EH_, H_, 128);
    k_xsum<<<B_*H_/256, 256>>>(bic);
    k_g64<<<dim3(3*H_/128, 8, 2), 256>>>(p_x, Wih, p_pgi, hidden, Whh, p_pgh,
                                         H_, 3*H_, 128);
    k_gates<<<B_*H_/256, 256>>>(hidden, bih, bhh, hnew);
    k_g64<<<dim3(H_/128, 8, 1), 256>>>(hnew, Wah, p_px, hnew, Wah, p_px,
                                       H_, H_, 128);
    k_basesum<<<B_*H_/256, 256>>>(bah, bas, bac);

    k_scores_mma<<<dim3(S_/128, B_), 256, SMEM_SC>>>(coverage, Wac, Wsq, bsq);
    k_attnsm<<<B_, S_>>>(coverage, story, out);
    k_ctx<<<dim3(H_/256, B_), 256>>>(ss, out);
    k_pgen<<<B_, 256>>>(Wpg, bpg, out);
    k_logits<<<V_/C4, 256>>>(hnew, out + OFF_CTX, Wout, bout);
    k_vocabsm<<<B_, 1024>>>(out);
}

// round 14
// speedup vs baseline: 3.2046x; 1.2296x over previous
#include <cuda_runtime.h>
#include <cuda_bf16.h>
#include <cstring>
#include <math.h>
#include <stdint.h>

#define S_  1024
#define B_  64
#define H_  1024
#define E_  512
#define V_  32000
#define EH_ 1536

typedef unsigned long long ull;

// ---------------- scratch (device globals; no runtime allocation) -------------
__device__ float g_x[B_*H_];
__device__ float g_base[B_*H_];
__device__ float g_scores[B_*S_];
__device__ float g_attn[B_*S_];
__device__ float g_logits[B_*V_];
__device__ float g_xcat[B_*EH_];
__device__ float g_px[12*B_*H_];
__device__ float g_pgi[8*B_*3*H_];
__device__ float g_pgh[8*B_*3*H_];
// tf32-rounded operands for the attention GEMM (32-bit containers)
__device__ unsigned int g_at[S_*B_*H_];   // ss  as tf32 (256 MB)
__device__ unsigned int g_wt[H_*H_];      // Was as tf32 (4 MB)

// ---------------- output layout ----------------------------------------------
#define OFF_PGEN  0
#define OFF_VOCAB 64
#define OFF_HNEW  (OFF_VOCAB + B_*V_)
#define OFF_CTX   (OFF_HNEW + B_*H_)
#define OFF_ATTN  (OFF_CTX  + B_*H_)
#define OFF_COV   (OFF_ATTN + B_*S_)

// ---------------- generic helpers --------------------------------------------
__device__ __forceinline__ void ffma2(ull& acc, ull a, ull b) {
    asm("fma.rn.f32x2 %0, %1, %2, %0;" : "+l"(acc) : "l"(a), "l"(b));
}
__device__ __forceinline__ ull pk2(float x, float y) {
    float2 f = make_float2(x, y); ull u; memcpy(&u, &f, 8); return u;
}
__device__ __forceinline__ float2 upk2(ull u) {
    float2 f; memcpy(&f, &u, 8); return f;
}
__device__ __forceinline__ float wredsum(float v) {
    #pragma unroll
    for (int o = 16; o; o >>= 1) v += __shfl_down_sync(0xffffffffu, v, o);
    return v;
}
__device__ __forceinline__ float wredmax(float v) {
    #pragma unroll
    for (int o = 16; o; o >>= 1) v = fmaxf(v, __shfl_down_sync(0xffffffffu, v, o));
    return v;
}
__device__ __forceinline__ float blockSum(float v, float* red) {
    int lane = threadIdx.x & 31, wid = threadIdx.x >> 5, nw = blockDim.x >> 5;
    v = wredsum(v);
    __syncthreads();
    if (lane == 0) red[wid] = v;
    __syncthreads();
    if (wid == 0) {
        float r = (lane < nw) ? red[lane] : 0.f;
        r = wredsum(r);
        if (lane == 0) red[0] = r;
    }
    __syncthreads();
    return red[0];
}
__device__ __forceinline__ float blockMax(float v, float* red) {
    int lane = threadIdx.x & 31, wid = threadIdx.x >> 5, nw = blockDim.x >> 5;
    v = wredmax(v);
    __syncthreads();
    if (lane == 0) red[wid] = v;
    __syncthreads();
    if (wid == 0) {
        float r = (lane < nw) ? red[lane] : -1e30f;
        r = wredmax(r);
        if (lane == 0) red[0] = r;
    }
    __syncthreads();
    return red[0];
}
__device__ __forceinline__ uint32_t smem_to_u32(const void* p) {
    uint32_t a;
    asm("{ .reg .u64 t; cvta.to.shared.u64 t, %1; cvt.u32.u64 %0, t; }"
        : "=r"(a) : "l"(p));
    return a;
}

// ---------------- MMA / async-copy helpers ------------------------------------
#define LDSM4(R, addr) \
    asm volatile("ldmatrix.sync.aligned.m8n8.x4.shared.b16 {%0,%1,%2,%3}, [%4];" \
        : "=r"((R)[0]), "=r"((R)[1]), "=r"((R)[2]), "=r"((R)[3]) : "r"(addr))

#define MMAT(D, A, Bp) \
    asm volatile("mma.sync.aligned.m16n8k8.row.col.f32.tf32.tf32.f32 " \
        "{%0,%1,%2,%3}, {%4,%5,%6,%7}, {%8,%9}, {%0,%1,%2,%3};" \
        : "+f"((D)[0]), "+f"((D)[1]), "+f"((D)[2]), "+f"((D)[3]) \
        : "r"((A)[0]), "r"((A)[1]), "r"((A)[2]), "r"((A)[3]), \
          "r"((Bp)[0]), "r"((Bp)[1]))

#define CPA16(dst, src) \
    asm volatile("cp.async.cg.shared.global [%0], [%1], 16;" \
        :: "r"(dst), "l"(src) : "memory")
#define CPA_COMMIT() asm volatile("cp.async.commit_group;" ::: "memory")
#define CPA_WAIT0()  asm volatile("cp.async.wait_group 0;" ::: "memory")

__device__ __forceinline__ unsigned int to_tf32(float x) {
    unsigned int r;
    asm("cvt.rna.tf32.f32 %0, %1;" : "=r"(r) : "f"(x));
    return r;
}

// ---------------- tf32 convert pre-passes -------------------------------------
__global__ void k_cvt_ss(const float* __restrict__ src) {
    int i = blockIdx.x * blockDim.x + threadIdx.x;
    float4 v = ((const float4*)src)[i];
    uint4 o;
    o.x = to_tf32(v.x); o.y = to_tf32(v.y);
    o.z = to_tf32(v.z); o.w = to_tf32(v.w);
    ((uint4*)g_at)[i] = o;
}
__global__ void k_cvt_was(const float* __restrict__ src) {
    int i = blockIdx.x * blockDim.x + threadIdx.x;
    float4 v = ((const float4*)src)[i];
    uint4 o;
    o.x = to_tf32(v.x); o.y = to_tf32(v.y);
    o.z = to_tf32(v.z); o.w = to_tf32(v.w);
    ((uint4*)g_wt)[i] = o;
}

// ---------------- batch-shared small GEMM (K-split partials) ------------------
__global__ __launch_bounds__(256) void k_g64(
    const float* __restrict__ A1, const float* __restrict__ W1, float* __restrict__ O1,
    const float* __restrict__ A2, const float* __restrict__ W2, float* __restrict__ O2,
    int lda, int Nld, int klen) {
    const float* A = blockIdx.z ? A2 : A1;
    const float* W = blockIdx.z ? W2 : W1;
    float*       O = blockIdx.z ? O2 : O1;
    __shared__ float am[64][32];
    __shared__ float wsm[32][132];
    int tid = threadIdx.x;
    int tx = tid & 15, ty = tid >> 4;
    int vc = blockIdx.x * 128;
    int kbeg = blockIdx.y * klen;
    int lr = tid >> 2, lk8 = tid & 3;
    int lc = tid >> 1, lh = tid & 1;
    ull acc[4][4];
    #pragma unroll
    for (int r = 0; r < 4; r++)
        #pragma unroll
        for (int j = 0; j < 4; j++) acc[r][j] = pk2(0.f, 0.f);

    for (int k0 = kbeg; k0 < kbeg + klen; k0 += 32) {
        __syncthreads();
        {
            const float* srcb = A + (long)lr * lda + k0;
            *(float4*)&am[lr][lk8 * 8]     = *(const float4*)(srcb + lk8 * 8);
            *(float4*)&am[lr][lk8 * 8 + 4] = *(const float4*)(srcb + lk8 * 8 + 4);
        }
        {
            const float4* src = (const float4*)(W + (long)(vc + lc) * lda + k0 + lh * 16);
            #pragma unroll
            for (int q = 0; q < 4; q++) {
                float4 v = src[q];
                int kk = lh * 16 + q * 4;
                wsm[kk + 0][lc] = v.x; wsm[kk + 1][lc] = v.y;
                wsm[kk + 2][lc] = v.z; wsm[kk + 3][lc] = v.w;
            }
        }
        __syncthreads();
        #pragma unroll
        for (int k = 0; k < 32; k++) {
            const ull* wp = (const ull*)&wsm[k][tx * 8];
            ull w0 = wp[0], w1 = wp[1], w2 = wp[2], w3 = wp[3];
            #pragma unroll
            for (int r = 0; r < 4; r++) {
                float av = am[ty + r * 16][k];
                ull aa = pk2(av, av);
                ffma2(acc[r][0], aa, w0); ffma2(acc[r][1], aa, w1);
                ffma2(acc[r][2], aa, w2); ffma2(acc[r][3], aa, w3);
            }
        }
    }
    long obase = (long)blockIdx.y * 64 * Nld;
    #pragma unroll
    for (int r = 0; r < 4; r++) {
        int brow = ty + r * 16;
        #pragma unroll
        for (int j = 0; j < 4; j++) {
            float2 f = upk2(acc[r][j]);
            int v = vc + tx * 8 + 2 * j;
            O[obase + (long)brow * Nld + v]     = f.x;
            O[obase + (long)brow * Nld + v + 1] = f.y;
        }
    }
}

// ---------------- small elementwise kernels -----------------------------------
__global__ void k_xcat(const float* __restrict__ etab, const int* __restrict__ ids,
                       const float* __restrict__ ctx) {
    int i = blockIdx.x * 256 + threadIdx.x;
    int r = i / 384, q = i % 384;
    float4 v = (q < 128) ? ((const float4*)(etab + (long)ids[r] * E_))[q]
                         : ((const float4*)(ctx + r * H_))[q - 128];
    ((float4*)g_xcat)[i] = v;
}
__global__ void k_xsum(const float* __restrict__ bic) {
    int i = blockIdx.x * 256 + threadIdx.x;
    float a = bic[i & 1023];
    #pragma unroll
    for (int p = 0; p < 12; p++) a += g_px[(long)p * B_ * H_ + i];
    g_x[i] = a;
}
__global__ void k_gates(const float* __restrict__ hidden, const float* __restrict__ bih,
                        const float* __restrict__ bhh, float* __restrict__ hnew) {
    int idx = blockIdx.x * 256 + threadIdx.x;
    int b = idx >> 10, i = idx & 1023;
    long o = (long)b * 3 * H_ + i;
    const long P = (long)B_ * 3 * H_;
    float ir = bih[i], iz = bih[i + H_], in_ = bih[i + 2*H_];
    float hr = bhh[i], hz = bhh[i + H_], hn  = bhh[i + 2*H_];
    #pragma unroll
    for (int p = 0; p < 8; p++) {
        long q = p * P + o;
        ir  += g_pgi[q];        iz += g_pgi[q + H_];    in_ += g_pgi[q + 2*H_];
        hr  += g_pgh[q];        hz += g_pgh[q + H_];    hn  += g_pgh[q + 2*H_];
    }
    float r = 1.f / (1.f + expf(-(ir + hr)));
    float z = 1.f / (1.f + expf(-(iz + hz)));
    float n = tanhf(in_ + r * hn);
    hnew[idx] = (1.f - z) * n + z * hidden[idx];
}
__global__ void k_basesum(const float* __restrict__ bah, const float* __restrict__ bas,
                          const float* __restrict__ bac) {
    int i = blockIdx.x * 256 + threadIdx.x;
    int h = i & 1023;
    float a = bah[h] + bas[h] + bac[h];
    #pragma unroll
    for (int p = 0; p < 8; p++) a += g_px[(long)p * B_ * H_ + i];
    g_base[i] = a;
}

// ---------------- K4: TF32 attention-score GEMM -------------------------------
// 128x128 tile, K-chunks of 32 f32 (128 B/row), 2-stage cp.async, 2 CTA/SM
#define ROWB 144                 // 128 data bytes + 16 pad (conflict-free)
#define ATILE (128*ROWB)         // 18432 B per operand tile
#define STAGE (2*ATILE)          // 36864 B per stage (A + B)
#define SMEM_SC (2*STAGE + 1024)

__device__ __forceinline__ void sc_copy(uint32_t sb, int stage, int b, int s0,
                                        int cc, int tid) {
    int np = cc >> 5, kc = cc & 31;
    int n0 = np * 128, k0 = kc * 32;
    uint32_t dst = sb + stage * STAGE;
    #pragma unroll
    for (int j = 0; j < 4; j++) {
        int c = tid + j * 256;              // 1024 16B-chunks per tile
        int row = c >> 3, q = c & 7;
        CPA16(dst + row * ROWB + q * 16,
              (const char*)(g_at + ((long)(s0 + row) * B_ + b) * H_ + k0 + q * 4));
        CPA16(dst + ATILE + row * ROWB + q * 16,
              (const char*)(g_wt + (long)(n0 + row) * H_ + k0 + q * 4));
    }
}

__global__ __launch_bounds__(256, 2) void k_scores_mma(
    const float* __restrict__ cov, const float* __restrict__ wac,
    const float* __restrict__ wsq, const float* __restrict__ bsq) {
    extern __shared__ __align__(16) char sm[];
    uint32_t sb = smem_to_u32(sm);
    float* red2 = (float*)(sm + 2 * STAGE);

    int tid = threadIdx.x, L = tid & 31, wid = tid >> 5;
    int wm = wid >> 1, wn = wid & 1;
    int b = blockIdx.y, s0 = blockIdx.x * 128;

    // ldmatrix lane offsets (b16 tiles reused for tf32 fragments)
    uint32_t aoff = ((L & 7) + ((L >> 3) & 1) * 8) * ROWB + ((L >> 4) & 1) * 16;
    uint32_t boff = ((L & 7) + ((L >> 4) & 1) * 8) * ROWB + ((L >> 3) & 1) * 16;

    float cov4[2][2];
    #pragma unroll
    for (int mt = 0; mt < 2; mt++)
        #pragma unroll
        for (int h = 0; h < 2; h++)
            cov4[mt][h] = cov[b * S_ + s0 + wm*32 + mt*16 + h*8 + (L >> 2)];

    float rs[2][2] = {{0.f, 0.f}, {0.f, 0.f}};
    float c[2][8][4];

    sc_copy(sb, 0, b, s0, 0, tid);
    CPA_COMMIT();

    for (int cc = 0; cc < 256; cc++) {
        int kc = cc & 31, np = cc >> 5;
        if (kc == 0) {
            #pragma unroll
            for (int mt = 0; mt < 2; mt++)
                #pragma unroll
                for (int nt = 0; nt < 8; nt++)
                    #pragma unroll
                    for (int j = 0; j < 4; j++) c[mt][nt][j] = 0.f;
        }
        CPA_WAIT0();
        __syncthreads();
        if (cc + 1 < 256) sc_copy(sb, (cc + 1) & 1, b, s0, cc + 1, tid);
        CPA_COMMIT();

        uint32_t st = sb + (cc & 1) * STAGE;
        uint32_t uA = st, uB = st + ATILE;
        #pragma unroll
        for (int ks = 0; ks < 4; ks++) {
            uint32_t kb = ks * 32;          // k8 tf32 = 32 bytes
            uint32_t a[2][4];
            #pragma unroll
            for (int mt = 0; mt < 2; mt++)
                LDSM4(a[mt], uA + (wm*32 + mt*16) * ROWB + kb + aoff);
            #pragma unroll
            for (int p = 0; p < 4; p++) {
                uint32_t bf[4];
                LDSM4(bf, uB + (wn*64 + p*16) * ROWB + kb + boff);
                #pragma unroll
                for (int mt = 0; mt < 2; mt++) {
                    #pragma unroll
                    for (int t = 0; t < 2; t++)
                        MMAT(c[mt][p*2 + t], a[mt], bf + t*2);
                }
            }
        }
        if (kc == 31) {
            int n0 = np * 128;
            #pragma unroll
            for (int mt = 0; mt < 2; mt++) {
                #pragma unroll
                for (int nt = 0; nt < 8; nt++) {
                    int g = n0 + wn*64 + nt*8 + (L & 3) * 2;
                    float q0 = wsq[g],  q1 = wsq[g + 1];
                    float e0 = g_base[b*H_ + g], e1 = g_base[b*H_ + g + 1];
                    float w0 = wac[g],  w1 = wac[g + 1];
                    rs[mt][0] += q0 * tanhf(c[mt][nt][0] + e0 + cov4[mt][0] * w0)
                               + q1 * tanhf(c[mt][nt][1] + e1 + cov4[mt][0] * w1);
                    rs[mt][1] += q0 * tanhf(c[mt][nt][2] + e0 + cov4[mt][1] * w0)
                               + q1 * tanhf(c[mt][nt][3] + e1 + cov4[mt][1] * w1);
                }
            }
        }
    }
    #pragma unroll
    for (int mt = 0; mt < 2; mt++)
        #pragma unroll
        for (int h = 0; h < 2; h++) {
            float v = rs[mt][h];
            v += __shfl_xor_sync(0xffffffffu, v, 1);
            v += __shfl_xor_sync(0xffffffffu, v, 2);
            rs[mt][h] = v;
        }
    __syncthreads();
    if ((L & 3) == 0) {
        #pragma unroll
        for (int mt = 0; mt < 2; mt++)
            #pragma unroll
            for (int h = 0; h < 2; h++)
                red2[wn*128 + wm*32 + mt*16 + h*8 + (L >> 2)] = rs[mt][h];
    }
    __syncthreads();
    if (tid < 128)
        g_scores[b * S_ + s0 + tid] = red2[tid] + red2[128 + tid] + bsq[0];
}

// ---------------- K5: attention softmax chain + coverage ---------------------
__global__ void k_attnsm(const float* __restrict__ coverage, const int* __restrict__ story,
                         float* __restrict__ out) {
    __shared__ float red[32];
    int b = blockIdx.x, t = threadIdx.x;
    float sc = g_scores[b * S_ + t];
    float m = (story[b * S_ + t] > 0) ? 1.f : 0.f;
    float mx = blockMax(sc, red);
    float e = expf(sc - mx);
    float sum = blockSum(e, red);
    float p = (e / sum) * m;
    float s2 = blockSum(p, red);
    float attn = p / s2;
    g_attn[b * S_ + t] = attn;
    out[OFF_COV + b * S_ + t] = coverage[b * S_ + t] + attn;
    float mx2 = blockMax(attn, red);
    float e2 = expf(attn - mx2);
    float s3 = blockSum(e2, red);
    out[OFF_ATTN + b * S_ + t] = e2 / s3;
}

// ---------------- K6: ctx = attn @ story_states ------------------------------
__global__ void k_ctx(const float* __restrict__ ss, float* __restrict__ out) {
    __shared__ float sa[S_];
    int b = blockIdx.y;
    int h = blockIdx.x * 256 + threadIdx.x;
    for (int i = threadIdx.x; i < S_; i += 256) sa[i] = g_attn[b * S_ + i];
    __syncthreads();
    float acc = 0.f;
    #pragma unroll 8
    for (int s = 0; s < S_; s++) acc += sa[s] * ss[((long)s * B_ + b) * H_ + h];
    out[OFF_CTX + b * H_ + h] = acc;
}

// ---------------- K7: pointer-gen gate ---------------------------------------
__global__ void k_pgen(const float* __restrict__ Wpg, const float* __restrict__ bpg,
                       float* __restrict__ out) {
    __shared__ float red[32];
    int b = blockIdx.x, t = threadIdx.x;
    float acc = 0.f;
    for (int k = t; k < H_; k += 256)
        acc += (g_x[b*H_ + k] + out[OFF_CTX + b*H_ + k] + out[OFF_HNEW + b*H_ + k]) * Wpg[k];
    float s = blockSum(acc, red);
    if (t == 0) out[OFF_PGEN + b] = 1.f / (1.f + expf(-(s + bpg[0])));
}

// ---------------- K8: vocab logits GEMM [64 x 32000, K=2048] -----------------
#define KT 32
#define C4 128
__global__ __launch_bounds__(256) void k_logits(
    const float* __restrict__ hnew, const float* __restrict__ ctx,
    const float* __restrict__ Wout, const float* __restrict__ bout) {
    __shared__ float am[64][KT];
    __shared__ float wsm[KT][C4 + 4];
    int tid = threadIdx.x;
    int tx = tid & 15, ty = tid >> 4;
    int vc = blockIdx.x * C4;
    int lr = tid >> 2, lk8 = tid & 3;
    int lc = tid >> 1, lh = tid & 1;
    ull acc[4][4];
    #pragma unroll
    for (int r = 0; r < 4; r++)
        #pragma unroll
        for (int j = 0; j < 4; j++) acc[r][j] = pk2(0.f, 0.f);

    for (int k0 = 0; k0 < 2 * H_; k0 += KT) {
        __syncthreads();
        {
            const float* srcb = (k0 < H_) ? (hnew + lr * H_ + k0)
                                          : (ctx + lr * H_ + (k0 - H_));
            *(float4*)&am[lr][lk8 * 8]     = *(const float4*)(srcb + lk8 * 8);
            *(float4*)&am[lr][lk8 * 8 + 4] = *(const float4*)(srcb + lk8 * 8 + 4);
        }
        {
            const float4* src = (const float4*)&Wout[(long)(vc + lc) * (2*H_) + k0 + lh * 16];
            #pragma unroll
            for (int q = 0; q < 4; q++) {
                float4 v = src[q];
                int kk = lh * 16 + q * 4;
                wsm[kk + 0][lc] = v.x; wsm[kk + 1][lc] = v.y;
                wsm[kk + 2][lc] = v.z; wsm[kk + 3][lc] = v.w;
            }
        }
        __syncthreads();
        #pragma unroll
        for (int k = 0; k < KT; k++) {
            const ull* wp = (const ull*)&wsm[k][tx * 8];
            ull w0 = wp[0], w1 = wp[1], w2 = wp[2], w3 = wp[3];
            #pragma unroll
            for (int r = 0; r < 4; r++) {
                float av = am[ty + r * 16][k];
                ull aa = pk2(av, av);
                ffma2(acc[r][0], aa, w0); ffma2(acc[r][1], aa, w1);
                ffma2(acc[r][2], aa, w2); ffma2(acc[r][3], aa, w3);
            }
        }
    }
    #pragma unroll
    for (int r = 0; r < 4; r++) {
        int brow = ty + r * 16;
        #pragma unroll
        for (int j = 0; j < 4; j++) {
            float2 f = upk2(acc[r][j]);
            int v = vc + tx * 8 + 2 * j;
            g_logits[(long)brow * V_ + v]     = f.x + bout[v];
            g_logits[(long)brow * V_ + v + 1] = f.y + bout[v + 1];
        }
    }
}

// ---------------- K9: vocab softmax ------------------------------------------
__global__ void k_vocabsm(float* __restrict__ out) {
    __shared__ float red[32];
    int b = blockIdx.x, t = threadIdx.x;
    const float* lg = g_logits + (long)b * V_;
    float* vo = out + OFF_VOCAB + (long)b * V_;
    float mx = -1e30f;
    for (int v = t; v < V_; v += 1024) mx = fmaxf(mx, lg[v]);
    mx = blockMax(mx, red);
    float sum = 0.f;
    for (int v = t; v < V_; v += 1024) { float e = expf(lg[v] - mx); vo[v] = e; sum += e; }
    sum = blockSum(sum, red);
    float inv = 1.f / sum;
    for (int v = t; v < V_; v += 1024) vo[v] *= inv;
}

// ---------------- launch ------------------------------------------------------
extern "C" void kernel_launch(void* const* d_in, const int* in_sizes, int n_in,
                              void* d_out, int out_size) {
    (void)in_sizes; (void)n_in; (void)out_size;
    const float* ss       = (const float*)d_in[0];
    const int*   story    = (const int*)  d_in[1];
    const int*   ids      = (const int*)  d_in[2];
    const float* hidden   = (const float*)d_in[3];
    const float* context  = (const float*)d_in[4];
    const float* coverage = (const float*)d_in[5];
    const float* etab     = (const float*)d_in[6];
    const float* Wic = (const float*)d_in[7];   const float* bic = (const float*)d_in[8];
    const float* Wah = (const float*)d_in[9];   const float* bah = (const float*)d_in[10];
    const float* Was = (const float*)d_in[11];  const float* bas = (const float*)d_in[12];
    const float* Wac = (const float*)d_in[13];  const float* bac = (const float*)d_in[14];
    const float* Wsq = (const float*)d_in[15];  const float* bsq = (const float*)d_in[16];
    const float* Wpg = (const float*)d_in[17];  const float* bpg = (const float*)d_in[18];
    const float* Wih = (const float*)d_in[19];  const float* Whh = (const float*)d_in[20];
    const float* bih = (const float*)d_in[21];  const float* bhh = (const float*)d_in[22];
    const float* Wout = (const float*)d_in[23]; const float* bout = (const float*)d_in[24];
    float* out = (float*)d_out;
    float* hnew = out + OFF_HNEW;

    static int smem_set = 0;
    if (!smem_set) {
        cudaFuncSetAttribute(k_scores_mma, cudaFuncAttributeMaxDynamicSharedMemorySize, SMEM_SC);
        smem_set = 1;
    }

    float *p_xcat, *p_x, *p_px, *p_pgi, *p_pgh;
    cudaGetSymbolAddress((void**)&p_xcat, g_xcat);
    cudaGetSymbolAddress((void**)&p_x,    g_x);
    cudaGetSymbolAddress((void**)&p_px,   g_px);
    cudaGetSymbolAddress((void**)&p_pgi,  g_pgi);
    cudaGetSymbolAddress((void**)&p_pgh,  g_pgh);

    k_cvt_ss <<<(S_*B_*H_/4)/256, 256>>>(ss);
    k_cvt_was<<<(H_*H_/4)/256, 256>>>(Was);

    k_xcat<<<(B_*EH_/4)/256, 256>>>(etab, ids, context);
    k_g64<<<dim3(H_/128, 12, 1), 256>>>(p_xcat, Wic, p_px, p_xcat, Wic, p_px,
                                        EH_, H_, 128);
    k_xsum<<<B_*H_/256, 256>>>(bic);
    k_g64<<<dim3(3*H_/128, 8, 2), 256>>>(p_x, Wih, p_pgi, hidden, Whh, p_pgh,
                                         H_, 3*H_, 128);
    k_gates<<<B_*H_/256, 256>>>(hidden, bih, bhh, hnew);
    k_g64<<<dim3(H_/128, 8, 1), 256>>>(hnew, Wah, p_px, hnew, Wah, p_px,
                                       H_, H_, 128);
    k_basesum<<<B_*H_/256, 256>>>(bah, bas, bac);

    k_scores_mma<<<dim3(S_/128, B_), 256, SMEM_SC>>>(coverage, Wac, Wsq, bsq);
    k_attnsm<<<B_, S_>>>(coverage, story, out);
    k_ctx<<<dim3(H_/256, B_), 256>>>(ss, out);
    k_pgen<<<B_, 256>>>(Wpg, bpg, out);
    k_logits<<<V_/C4, 256>>>(hnew, out + OFF_CTX, Wout, bout);
    k_vocabsm<<<B_, 1024>>>(out);
}

// round 15
// speedup vs baseline: 5.4667x; 1.7059x over previous
#include <cuda_runtime.h>
#include <cuda_fp16.h>
#include <cstring>
#include <math.h>
#include <stdint.h>

#define S_  1024
#define B_  64
#define H_  1024
#define E_  512
#define V_  32000
#define EH_ 1536

typedef unsigned long long ull;

// ---------------- scratch (device globals; no runtime allocation) -------------
__device__ float g_x[B_*H_];
__device__ float g_base[B_*H_];
__device__ float g_scores[B_*S_];
__device__ float g_attn[B_*S_];
__device__ float g_logits[B_*V_];
__device__ float g_xcat[B_*EH_];
__device__ float g_px[12*B_*H_];
__device__ float g_pgi[8*B_*3*H_];
__device__ float g_pgh[8*B_*3*H_];
// f16 operands for the attention GEMM
__device__ unsigned short g_hA[S_*B_*H_];   // ss  as f16 (128 MB)
__device__ unsigned short g_hW[H_*H_];      // Was as f16 (2 MB)

// ---------------- output layout ----------------------------------------------
#define OFF_PGEN  0
#define OFF_VOCAB 64
#define OFF_HNEW  (OFF_VOCAB + B_*V_)
#define OFF_CTX   (OFF_HNEW + B_*H_)
#define OFF_ATTN  (OFF_CTX  + B_*H_)
#define OFF_COV   (OFF_ATTN + B_*S_)

// ---------------- generic helpers --------------------------------------------
__device__ __forceinline__ void ffma2(ull& acc, ull a, ull b) {
    asm("fma.rn.f32x2 %0, %1, %2, %0;" : "+l"(acc) : "l"(a), "l"(b));
}
__device__ __forceinline__ ull pk2(float x, float y) {
    float2 f = make_float2(x, y); ull u; memcpy(&u, &f, 8); return u;
}
__device__ __forceinline__ float2 upk2(ull u) {
    float2 f; memcpy(&f, &u, 8); return f;
}
__device__ __forceinline__ float wredsum(float v) {
    #pragma unroll
    for (int o = 16; o; o >>= 1) v += __shfl_down_sync(0xffffffffu, v, o);
    return v;
}
__device__ __forceinline__ float wredmax(float v) {
    #pragma unroll
    for (int o = 16; o; o >>= 1) v = fmaxf(v, __shfl_down_sync(0xffffffffu, v, o));
    return v;
}
__device__ __forceinline__ float blockSum(float v, float* red) {
    int lane = threadIdx.x & 31, wid = threadIdx.x >> 5, nw = blockDim.x >> 5;
    v = wredsum(v);
    __syncthreads();
    if (lane == 0) red[wid] = v;
    __syncthreads();
    if (wid == 0) {
        float r = (lane < nw) ? red[lane] : 0.f;
        r = wredsum(r);
        if (lane == 0) red[0] = r;
    }
    __syncthreads();
    return red[0];
}
__device__ __forceinline__ float blockMax(float v, float* red) {
    int lane = threadIdx.x & 31, wid = threadIdx.x >> 5, nw = blockDim.x >> 5;
    v = wredmax(v);
    __syncthreads();
    if (lane == 0) red[wid] = v;
    __syncthreads();
    if (wid == 0) {
        float r = (lane < nw) ? red[lane] : -1e30f;
        r = wredmax(r);
        if (lane == 0) red[0] = r;
    }
    __syncthreads();
    return red[0];
}
__device__ __forceinline__ uint32_t smem_to_u32(const void* p) {
    uint32_t a;
    asm("{ .reg .u64 t; cvta.to.shared.u64 t, %1; cvt.u32.u64 %0, t; }"
        : "=r"(a) : "l"(p));
    return a;
}

// ---------------- MMA / async-copy helpers ------------------------------------
#define LDSM4(R, addr) \
    asm volatile("ldmatrix.sync.aligned.m8n8.x4.shared.b16 {%0,%1,%2,%3}, [%4];" \
        : "=r"((R)[0]), "=r"((R)[1]), "=r"((R)[2]), "=r"((R)[3]) : "r"(addr))

#define MMAH(D, A, Bp) \
    asm volatile("mma.sync.aligned.m16n8k16.row.col.f32.f16.f16.f32 " \
        "{%0,%1,%2,%3}, {%4,%5,%6,%7}, {%8,%9}, {%0,%1,%2,%3};" \
        : "+f"((D)[0]), "+f"((D)[1]), "+f"((D)[2]), "+f"((D)[3]) \
        : "r"((A)[0]), "r"((A)[1]), "r"((A)[2]), "r"((A)[3]), \
          "r"((Bp)[0]), "r"((Bp)[1]))

#define CPA16(dst, src) \
    asm volatile("cp.async.cg.shared.global [%0], [%1], 16;" \
        :: "r"(dst), "l"(src) : "memory")
#define CPA_COMMIT() asm volatile("cp.async.commit_group;" ::: "memory")
#define CPA_WAIT0()  asm volatile("cp.async.wait_group 0;" ::: "memory")

__device__ __forceinline__ unsigned short f2h(float x) {
    __half h = __float2half_rn(x);
    return *reinterpret_cast<unsigned short*>(&h);
}

// ---------------- f16 convert pre-passes --------------------------------------
__global__ void k_cvt_ss(const float* __restrict__ src) {
    int i = blockIdx.x * blockDim.x + threadIdx.x;
    float4 v = ((const float4*)src)[i];
    ushort4 o;
    o.x = f2h(v.x); o.y = f2h(v.y); o.z = f2h(v.z); o.w = f2h(v.w);
    ((ushort4*)g_hA)[i] = o;
}
__global__ void k_cvt_was(const float* __restrict__ src) {
    int i = blockIdx.x * blockDim.x + threadIdx.x;
    float4 v = ((const float4*)src)[i];
    ushort4 o;
    o.x = f2h(v.x); o.y = f2h(v.y); o.z = f2h(v.z); o.w = f2h(v.w);
    ((ushort4*)g_hW)[i] = o;
}

// ---------------- batch-shared small GEMM (K-split partials) ------------------
__global__ __launch_bounds__(256) void k_g64(
    const float* __restrict__ A1, const float* __restrict__ W1, float* __restrict__ O1,
    const float* __restrict__ A2, const float* __restrict__ W2, float* __restrict__ O2,
    int lda, int Nld, int klen) {
    const float* A = blockIdx.z ? A2 : A1;
    const float* W = blockIdx.z ? W2 : W1;
    float*       O = blockIdx.z ? O2 : O1;
    __shared__ float am[64][32];
    __shared__ float wsm[32][132];
    int tid = threadIdx.x;
    int tx = tid & 15, ty = tid >> 4;
    int vc = blockIdx.x * 128;
    int kbeg = blockIdx.y * klen;
    int lr = tid >> 2, lk8 = tid & 3;
    int lc = tid >> 1, lh = tid & 1;
    ull acc[4][4];
    #pragma unroll
    for (int r = 0; r < 4; r++)
        #pragma unroll
        for (int j = 0; j < 4; j++) acc[r][j] = pk2(0.f, 0.f);

    for (int k0 = kbeg; k0 < kbeg + klen; k0 += 32) {
        __syncthreads();
        {
            const float* srcb = A + (long)lr * lda + k0;
            *(float4*)&am[lr][lk8 * 8]     = *(const float4*)(srcb + lk8 * 8);
            *(float4*)&am[lr][lk8 * 8 + 4] = *(const float4*)(srcb + lk8 * 8 + 4);
        }
        {
            const float4* src = (const float4*)(W + (long)(vc + lc) * lda + k0 + lh * 16);
            #pragma unroll
            for (int q = 0; q < 4; q++) {
                float4 v = src[q];
                int kk = lh * 16 + q * 4;
                wsm[kk + 0][lc] = v.x; wsm[kk + 1][lc] = v.y;
                wsm[kk + 2][lc] = v.z; wsm[kk + 3][lc] = v.w;
            }
        }
        __syncthreads();
        #pragma unroll
        for (int k = 0; k < 32; k++) {
            const ull* wp = (const ull*)&wsm[k][tx * 8];
            ull w0 = wp[0], w1 = wp[1], w2 = wp[2], w3 = wp[3];
            #pragma unroll
            for (int r = 0; r < 4; r++) {
                float av = am[ty + r * 16][k];
                ull aa = pk2(av, av);
                ffma2(acc[r][0], aa, w0); ffma2(acc[r][1], aa, w1);
                ffma2(acc[r][2], aa, w2); ffma2(acc[r][3], aa, w3);
            }
        }
    }
    long obase = (long)blockIdx.y * 64 * Nld;
    #pragma unroll
    for (int r = 0; r < 4; r++) {
        int brow = ty + r * 16;
        #pragma unroll
        for (int j = 0; j < 4; j++) {
            float2 f = upk2(acc[r][j]);
            int v = vc + tx * 8 + 2 * j;
            O[obase + (long)brow * Nld + v]     = f.x;
            O[obase + (long)brow * Nld + v + 1] = f.y;
        }
    }
}

// ---------------- small elementwise kernels -----------------------------------
__global__ void k_xcat(const float* __restrict__ etab, const int* __restrict__ ids,
                       const float* __restrict__ ctx) {
    int i = blockIdx.x * 256 + threadIdx.x;
    int r = i / 384, q = i % 384;
    float4 v = (q < 128) ? ((const float4*)(etab + (long)ids[r] * E_))[q]
                         : ((const float4*)(ctx + r * H_))[q - 128];
    ((float4*)g_xcat)[i] = v;
}
__global__ void k_xsum(const float* __restrict__ bic) {
    int i = blockIdx.x * 256 + threadIdx.x;
    float a = bic[i & 1023];
    #pragma unroll
    for (int p = 0; p < 12; p++) a += g_px[(long)p * B_ * H_ + i];
    g_x[i] = a;
}
__global__ void k_gates(const float* __restrict__ hidden, const float* __restrict__ bih,
                        const float* __restrict__ bhh, float* __restrict__ hnew) {
    int idx = blockIdx.x * 256 + threadIdx.x;
    int b = idx >> 10, i = idx & 1023;
    long o = (long)b * 3 * H_ + i;
    const long P = (long)B_ * 3 * H_;
    float ir = bih[i], iz = bih[i + H_], in_ = bih[i + 2*H_];
    float hr = bhh[i], hz = bhh[i + H_], hn  = bhh[i + 2*H_];
    #pragma unroll
    for (int p = 0; p < 8; p++) {
        long q = p * P + o;
        ir  += g_pgi[q];        iz += g_pgi[q + H_];    in_ += g_pgi[q + 2*H_];
        hr  += g_pgh[q];        hz += g_pgh[q + H_];    hn  += g_pgh[q + 2*H_];
    }
    float r = 1.f / (1.f + expf(-(ir + hr)));
    float z = 1.f / (1.f + expf(-(iz + hz)));
    float n = tanhf(in_ + r * hn);
    hnew[idx] = (1.f - z) * n + z * hidden[idx];
}
__global__ void k_basesum(const float* __restrict__ bah, const float* __restrict__ bas,
                          const float* __restrict__ bac) {
    int i = blockIdx.x * 256 + threadIdx.x;
    int h = i & 1023;
    float a = bah[h] + bas[h] + bac[h];
    #pragma unroll
    for (int p = 0; p < 8; p++) a += g_px[(long)p * B_ * H_ + i];
    g_base[i] = a;
}

// ---------------- K4: single-pass f16 HMMA attention-score GEMM ---------------
// 128x128 tile, K-chunks of 32 f16 (64 B/row + 16 pad), 2-stage cp.async, 2 CTA/SM
#define ROWB 80
#define ATILE (128*ROWB)         // 10240 B per operand tile
#define STAGE (2*ATILE)          // 20480 B per stage (A + B)
#define SMEM_SC (2*STAGE + 1024)

__device__ __forceinline__ void sc_copy(uint32_t sb, int stage, int b, int s0,
                                        int cc, int tid) {
    int np = cc >> 5, kc = cc & 31;
    int n0 = np * 128, k0 = kc * 32;
    uint32_t dst = sb + stage * STAGE;
    #pragma unroll
    for (int j = 0; j < 4; j++) {
        int c = tid + j * 256;          // 1024 16B-chunks (512 A + 512 B)
        int arr = c >> 9;
        int r = (c >> 2) & 127, q = c & 3;
        if (arr == 0) {
            CPA16(dst + r * ROWB + q * 16,
                  (const char*)(g_hA + ((long)(s0 + r) * B_ + b) * H_ + k0 + q * 8));
        } else {
            CPA16(dst + ATILE + r * ROWB + q * 16,
                  (const char*)(g_hW + (long)(n0 + r) * H_ + k0 + q * 8));
        }
    }
}

__global__ __launch_bounds__(256, 2) void k_scores_mma(
    const float* __restrict__ cov, const float* __restrict__ wac,
    const float* __restrict__ wsq, const float* __restrict__ bsq) {
    extern __shared__ __align__(16) char sm[];
    uint32_t sb = smem_to_u32(sm);
    float* red2 = (float*)(sm + 2 * STAGE);

    int tid = threadIdx.x, L = tid & 31, wid = tid >> 5;
    int wm = wid >> 1, wn = wid & 1;
    int b = blockIdx.y, s0 = blockIdx.x * 128;

    uint32_t aoff = ((L & 7) + ((L >> 3) & 1) * 8) * ROWB + ((L >> 4) & 1) * 16;
    uint32_t boff = ((L & 7) + ((L >> 4) & 1) * 8) * ROWB + ((L >> 3) & 1) * 16;

    float cov4[2][2];
    #pragma unroll
    for (int mt = 0; mt < 2; mt++)
        #pragma unroll
        for (int h = 0; h < 2; h++)
            cov4[mt][h] = cov[b * S_ + s0 + wm*32 + mt*16 + h*8 + (L >> 2)];

    float rs[2][2] = {{0.f, 0.f}, {0.f, 0.f}};
    float c[2][8][4];

    sc_copy(sb, 0, b, s0, 0, tid);
    CPA_COMMIT();

    for (int cc = 0; cc < 256; cc++) {
        int kc = cc & 31, np = cc >> 5;
        if (kc == 0) {
            #pragma unroll
            for (int mt = 0; mt < 2; mt++)
                #pragma unroll
                for (int nt = 0; nt < 8; nt++)
                    #pragma unroll
                    for (int j = 0; j < 4; j++) c[mt][nt][j] = 0.f;
        }
        CPA_WAIT0();
        __syncthreads();
        if (cc + 1 < 256) sc_copy(sb, (cc + 1) & 1, b, s0, cc + 1, tid);
        CPA_COMMIT();

        uint32_t st = sb + (cc & 1) * STAGE;
        uint32_t uA = st, uB = st + ATILE;
        #pragma unroll
        for (int ks = 0; ks < 2; ks++) {
            uint32_t kb = ks * 32;          // k16 f16 = 32 bytes
            uint32_t a[2][4];
            #pragma unroll
            for (int mt = 0; mt < 2; mt++)
                LDSM4(a[mt], uA + (wm*32 + mt*16) * ROWB + kb + aoff);
            #pragma unroll
            for (int p = 0; p < 4; p++) {
                uint32_t bf[4];
                LDSM4(bf, uB + (wn*64 + p*16) * ROWB + kb + boff);
                #pragma unroll
                for (int mt = 0; mt < 2; mt++) {
                    #pragma unroll
                    for (int t = 0; t < 2; t++)
                        MMAH(c[mt][p*2 + t], a[mt], bf + t*2);
                }
            }
        }
        if (kc == 31) {
            int n0 = np * 128;
            #pragma unroll
            for (int mt = 0; mt < 2; mt++) {
                #pragma unroll
                for (int nt = 0; nt < 8; nt++) {
                    int g = n0 + wn*64 + nt*8 + (L & 3) * 2;
                    float q0 = wsq[g],  q1 = wsq[g + 1];
                    float e0 = g_base[b*H_ + g], e1 = g_base[b*H_ + g + 1];
                    float w0 = wac[g],  w1 = wac[g + 1];
                    rs[mt][0] += q0 * tanhf(c[mt][nt][0] + e0 + cov4[mt][0] * w0)
                               + q1 * tanhf(c[mt][nt][1] + e1 + cov4[mt][0] * w1);
                    rs[mt][1] += q0 * tanhf(c[mt][nt][2] + e0 + cov4[mt][1] * w0)
                               + q1 * tanhf(c[mt][nt][3] + e1 + cov4[mt][1] * w1);
                }
            }
        }
    }
    #pragma unroll
    for (int mt = 0; mt < 2; mt++)
        #pragma unroll
        for (int h = 0; h < 2; h++) {
            float v = rs[mt][h];
            v += __shfl_xor_sync(0xffffffffu, v, 1);
            v += __shfl_xor_sync(0xffffffffu, v, 2);
            rs[mt][h] = v;
        }
    __syncthreads();
    if ((L & 3) == 0) {
        #pragma unroll
        for (int mt = 0; mt < 2; mt++)
            #pragma unroll
            for (int h = 0; h < 2; h++)
                red2[wn*128 + wm*32 + mt*16 + h*8 + (L >> 2)] = rs[mt][h];
    }
    __syncthreads();
    if (tid < 128)
        g_scores[b * S_ + s0 + tid] = red2[tid] + red2[128 + tid] + bsq[0];
}

// ---------------- K5: attention softmax chain + coverage ---------------------
__global__ void k_attnsm(const float* __restrict__ coverage, const int* __restrict__ story,
                         float* __restrict__ out) {
    __shared__ float red[32];
    int b = blockIdx.x, t = threadIdx.x;
    float sc = g_scores[b * S_ + t];
    float m = (story[b * S_ + t] > 0) ? 1.f : 0.f;
    float mx = blockMax(sc, red);
    float e = expf(sc - mx);
    float sum = blockSum(e, red);
    float p = (e / sum) * m;
    float s2 = blockSum(p, red);
    float attn = p / s2;
    g_attn[b * S_ + t] = attn;
    out[OFF_COV + b * S_ + t] = coverage[b * S_ + t] + attn;
    float mx2 = blockMax(attn, red);
    float e2 = expf(attn - mx2);
    float s3 = blockSum(e2, red);
    out[OFF_ATTN + b * S_ + t] = e2 / s3;
}

// ---------------- K6: ctx = attn @ story_states ------------------------------
__global__ void k_ctx(const float* __restrict__ ss, float* __restrict__ out) {
    __shared__ float sa[S_];
    int b = blockIdx.y;
    int h = blockIdx.x * 256 + threadIdx.x;
    for (int i = threadIdx.x; i < S_; i += 256) sa[i] = g_attn[b * S_ + i];
    __syncthreads();
    float acc = 0.f;
    #pragma unroll 8
    for (int s = 0; s < S_; s++) acc += sa[s] * ss[((long)s * B_ + b) * H_ + h];
    out[OFF_CTX + b * H_ + h] = acc;
}

// ---------------- K7: pointer-gen gate ---------------------------------------
__global__ void k_pgen(const float* __restrict__ Wpg, const float* __restrict__ bpg,
                       float* __restrict__ out) {
    __shared__ float red[32];
    int b = blockIdx.x, t = threadIdx.x;
    float acc = 0.f;
    for (int k = t; k < H_; k += 256)
        acc += (g_x[b*H_ + k] + out[OFF_CTX + b*H_ + k] + out[OFF_HNEW + b*H_ + k]) * Wpg[k];
    float s = blockSum(acc, red);
    if (t == 0) out[OFF_PGEN + b] = 1.f / (1.f + expf(-(s + bpg[0])));
}

// ---------------- K8: vocab logits via f16 HMMA [64 x 32000, K=2048] ----------
#define LROWB 80
__global__ __launch_bounds__(256) void k_logits(
    const float* __restrict__ hnew, const float* __restrict__ ctx,
    const float* __restrict__ Wout, const float* __restrict__ bout) {
    __shared__ __align__(16) unsigned short Asm[64 * 40];    // 64 x 32 f16, ROWB 80
    __shared__ __align__(16) unsigned short Bsm[128 * 40];   // 128 x 32 f16
    uint32_t uA = smem_to_u32(Asm), uB = smem_to_u32(Bsm);
    int tid = threadIdx.x, L = tid & 31, wid = tid >> 5;
    int wm = wid >> 2, wn = wid & 3;
    int vc = blockIdx.x * 128;

    uint32_t aoff = ((L & 7) + ((L >> 3) & 1) * 8) * LROWB + ((L >> 4) & 1) * 16;
    uint32_t boff = ((L & 7) + ((L >> 4) & 1) * 8) * LROWB + ((L >> 3) & 1) * 16;

    float c[2][4][4];
    #pragma unroll
    for (int mt = 0; mt < 2; mt++)
        #pragma unroll
        for (int nt = 0; nt < 4; nt++)
            #pragma unroll
            for (int j = 0; j < 4; j++) c[mt][nt][j] = 0.f;

    for (int ch = 0; ch < 64; ch++) {
        int k0 = ch * 32;
        __syncthreads();
        {   // A: 64 x 32, cvt f32->f16
            int r = tid >> 2, c8 = (tid & 3) * 8;
            const float* srcb = (k0 < H_) ? (hnew + r * H_ + k0 + c8)
                                          : (ctx + r * H_ + (k0 - H_) + c8);
            float4 v0 = *(const float4*)srcb;
            float4 v1 = *(const float4*)(srcb + 4);
            ushort4 h0 = { f2h(v0.x), f2h(v0.y), f2h(v0.z), f2h(v0.w) };
            ushort4 h1 = { f2h(v1.x), f2h(v1.y), f2h(v1.z), f2h(v1.w) };
            *(ushort4*)((char*)Asm + r * LROWB + c8 * 2)     = h0;
            *(ushort4*)((char*)Asm + r * LROWB + c8 * 2 + 8) = h1;
        }
        {   // B: 128 x 32 from Wout, cvt f32->f16
            int r = tid >> 1, h16 = (tid & 1) * 16;
            const float* ws = Wout + (long)(vc + r) * (2 * H_) + k0 + h16;
            #pragma unroll
            for (int q = 0; q < 2; q++) {
                float4 v0 = *(const float4*)(ws + q * 8);
                float4 v1 = *(const float4*)(ws + q * 8 + 4);
                ushort4 h0 = { f2h(v0.x), f2h(v0.y), f2h(v0.z), f2h(v0.w) };
                ushort4 h1 = { f2h(v1.x), f2h(v1.y), f2h(v1.z), f2h(v1.w) };
                *(ushort4*)((char*)Bsm + r * LROWB + h16 * 2 + q * 16)     = h0;
                *(ushort4*)((char*)Bsm + r * LROWB + h16 * 2 + q * 16 + 8) = h1;
            }
        }
        __syncthreads();
        #pragma unroll
        for (int ks = 0; ks < 2; ks++) {
            uint32_t kb = ks * 32;
            uint32_t a[2][4];
            #pragma unroll
            for (int mt = 0; mt < 2; mt++)
                LDSM4(a[mt], uA + (wm*32 + mt*16) * LROWB + kb + aoff);
            #pragma unroll
            for (int p = 0; p < 2; p++) {
                uint32_t bf[4];
                LDSM4(bf, uB + (wn*32 + p*16) * LROWB + kb + boff);
                #pragma unroll
                for (int mt = 0; mt < 2; mt++) {
                    #pragma unroll
                    for (int t = 0; t < 2; t++)
                        MMAH(c[mt][p*2 + t], a[mt], bf + t*2);
                }
            }
        }
    }
    #pragma unroll
    for (int mt = 0; mt < 2; mt++) {
        #pragma unroll
        for (int nt = 0; nt < 4; nt++) {
            int g = vc + wn*32 + nt*8 + (L & 3) * 2;
            int r0 = wm*32 + mt*16 + (L >> 2);
            int r1 = r0 + 8;
            g_logits[(long)r0 * V_ + g]     = c[mt][nt][0] + bout[g];
            g_logits[(long)r0 * V_ + g + 1] = c[mt][nt][1] + bout[g + 1];
            g_logits[(long)r1 * V_ + g]     = c[mt][nt][2] + bout[g];
            g_logits[(long)r1 * V_ + g + 1] = c[mt][nt][3] + bout[g + 1];
        }
    }
}

// ---------------- K9: vocab softmax ------------------------------------------
__global__ void k_vocabsm(float* __restrict__ out) {
    __shared__ float red[32];
    int b = blockIdx.x, t = threadIdx.x;
    const float* lg = g_logits + (long)b * V_;
    float* vo = out + OFF_VOCAB + (long)b * V_;
    float mx = -1e30f;
    for (int v = t; v < V_; v += 1024) mx = fmaxf(mx, lg[v]);
    mx = blockMax(mx, red);
    float sum = 0.f;
    for (int v = t; v < V_; v += 1024) { float e = expf(lg[v] - mx); vo[v] = e; sum += e; }
    sum = blockSum(sum, red);
    float inv = 1.f / sum;
    for (int v = t; v < V_; v += 1024) vo[v] *= inv;
}

// ---------------- launch ------------------------------------------------------
extern "C" void kernel_launch(void* const* d_in, const int* in_sizes, int n_in,
                              void* d_out, int out_size) {
    (void)in_sizes; (void)n_in; (void)out_size;
    const float* ss       = (const float*)d_in[0];
    const int*   story    = (const int*)  d_in[1];
    const int*   ids      = (const int*)  d_in[2];
    const float* hidden   = (const float*)d_in[3];
    const float* context  = (const float*)d_in[4];
    const float* coverage = (const float*)d_in[5];
    const float* etab     = (const float*)d_in[6];
    const float* Wic = (const float*)d_in[7];   const float* bic = (const float*)d_in[8];
    const float* Wah = (const float*)d_in[9];   const float* bah = (const float*)d_in[10];
    const float* Was = (const float*)d_in[11];  const float* bas = (const float*)d_in[12];
    const float* Wac = (const float*)d_in[13];  const float* bac = (const float*)d_in[14];
    const float* Wsq = (const float*)d_in[15];  const float* bsq = (const float*)d_in[16];
    const float* Wpg = (const float*)d_in[17];  const float* bpg = (const float*)d_in[18];
    const float* Wih = (const float*)d_in[19];  const float* Whh = (const float*)d_in[20];
    const float* bih = (const float*)d_in[21];  const float* bhh = (const float*)d_in[22];
    const float* Wout = (const float*)d_in[23]; const float* bout = (const float*)d_in[24];
    float* out = (float*)d_out;
    float* hnew = out + OFF_HNEW;

    static int smem_set = 0;
    if (!smem_set) {
        cudaFuncSetAttribute(k_scores_mma, cudaFuncAttributeMaxDynamicSharedMemorySize, SMEM_SC);
        smem_set = 1;
    }

    float *p_xcat, *p_x, *p_px, *p_pgi, *p_pgh;
    cudaGetSymbolAddress((void**)&p_xcat, g_xcat);
    cudaGetSymbolAddress((void**)&p_x,    g_x);
    cudaGetSymbolAddress((void**)&p_px,   g_px);
    cudaGetSymbolAddress((void**)&p_pgi,  g_pgi);
    cudaGetSymbolAddress((void**)&p_pgh,  g_pgh);

    k_cvt_ss <<<(S_*B_*H_/4)/256, 256>>>(ss);
    k_cvt_was<<<(H_*H_/4)/256, 256>>>(Was);

    k_xcat<<<(B_*EH_/4)/256, 256>>>(etab, ids, context);
    k_g64<<<dim3(H_/128, 12, 1), 256>>>(p_xcat, Wic, p_px, p_xcat, Wic, p_px,
                                        EH_, H_, 128);
    k_xsum<<<B_*H_/256, 256>>>(bic);
    k_g64<<<dim3(3*H_/128, 8, 2), 256>>>(p_x, Wih, p_pgi, hidden, Whh, p_pgh,
                                         H_, 3*H_, 128);
    k_gates<<<B_*H_/256, 256>>>(hidden, bih, bhh, hnew);
    k_g64<<<dim3(H_/128, 8, 1), 256>>>(hnew, Wah, p_px, hnew, Wah, p_px,
                                       H_, H_, 128);
    k_basesum<<<B_*H_/256, 256>>>(bah, bas, bac);

    k_scores_mma<<<dim3(S_/128, B_), 256, SMEM_SC>>>(coverage, Wac, Wsq, bsq);
    k_attnsm<<<B_, S_>>>(coverage, story, out);
    k_ctx<<<dim3(H_/256, B_), 256>>>(ss, out);
    k_pgen<<<B_, 256>>>(Wpg, bpg, out);
    k_logits<<<V_/128, 256>>>(hnew, out + OFF_CTX, Wout, bout);
    k_vocabsm<<<B_, 1024>>>(out);
}